// round 3
// baseline (speedup 1.0000x reference)
#include <cuda_runtime.h>
#include <math.h>

#define CDIV(a,b) (((a)+(b)-1)/(b))

static constexpr int B  = 32;
static constexpr int KN = 16;     // neighborhood size
static constexpr int N0 = 2048, N1 = 512, N2 = 128;

// ---------------- scratch (device globals; no allocation allowed) ----------------
static constexpr size_t OFF_F0  = 0;                                  // B*8*N0
static constexpr size_t OFF_G1  = OFF_F0  + (size_t)B*8*N0;           // B*N0*32
static constexpr size_t OFF_H1  = OFF_G1  + (size_t)B*N0*32;          // B*N0*32
static constexpr size_t OFF_M1  = OFF_H1  + (size_t)B*N0*32;
static constexpr size_t OFF_MN1 = OFF_M1  + (size_t)B*N0*32;
static constexpr size_t OFF_F1  = OFF_MN1 + (size_t)B*N0*32;          // B*32*N0
static constexpr size_t OFF_CQ1 = OFF_F1  + (size_t)B*32*N0;          // B*3*N1
static constexpr size_t OFF_FQ1 = OFF_CQ1 + (size_t)B*3*N1;           // B*32*N1
static constexpr size_t OFF_G2  = OFF_FQ1 + (size_t)B*32*N1;          // B*N0*64
static constexpr size_t OFF_H2  = OFF_G2  + (size_t)B*N0*64;          // B*N1*64
static constexpr size_t OFF_M2  = OFF_H2  + (size_t)B*N1*64;
static constexpr size_t OFF_MN2 = OFF_M2  + (size_t)B*N1*64;
static constexpr size_t OFF_F2  = OFF_MN2 + (size_t)B*N1*64;          // B*64*N1
static constexpr size_t OFF_G3  = OFF_F2  + (size_t)B*64*N1;          // B*N1*64
static constexpr size_t OFF_H3  = OFF_G3  + (size_t)B*N1*64;
static constexpr size_t OFF_M3  = OFF_H3  + (size_t)B*N1*64;
static constexpr size_t OFF_MN3 = OFF_M3  + (size_t)B*N1*64;
static constexpr size_t OFF_F3  = OFF_MN3 + (size_t)B*N1*64;          // B*64*N1
static constexpr size_t OFF_FQ3 = OFF_F3  + (size_t)B*64*N1;          // B*64*N2
static constexpr size_t OFF_G4  = OFF_FQ3 + (size_t)B*64*N2;          // B*N1*128
static constexpr size_t OFF_H4  = OFF_G4  + (size_t)B*N1*128;         // B*N2*128
static constexpr size_t OFF_M4  = OFF_H4  + (size_t)B*N2*128;
static constexpr size_t OFF_MN4 = OFF_M4  + (size_t)B*N2*128;
static constexpr size_t FBUF_TOTAL = OFF_MN4 + (size_t)B*N2*128;

__device__ float d_fbuf[FBUF_TOTAL];

static constexpr size_t IOFF_IDX1 = 0;                                // B*N0*KN
static constexpr size_t IOFF_FPS1 = IOFF_IDX1 + (size_t)B*N0*KN;      // B*N1
static constexpr size_t IOFF_IDX2 = IOFF_FPS1 + (size_t)B*N1;         // B*N1*KN
static constexpr size_t IOFF_IDX3 = IOFF_IDX2 + (size_t)B*N1*KN;      // B*N1*KN
static constexpr size_t IOFF_FPS2 = IOFF_IDX3 + (size_t)B*N1*KN;      // B*N2
static constexpr size_t IOFF_IDX4 = IOFF_FPS2 + (size_t)B*N2;         // B*N2*KN
static constexpr size_t IBUF_TOTAL = IOFF_IDX4 + (size_t)B*N2*KN;

__device__ int d_ibuf[IBUF_TOTAL];
__device__ double d_statsbuf[4 * B * 4 * 2];   // [layer][b][group][{sum,sumsq}]

// ---------------- kernels ----------------

__global__ void k_zero_stats(double* p, int n) {
    int t = blockIdx.x * blockDim.x + threadIdx.x;
    if (t < n) p[t] = 0.0;
}

// f0[b,o,n] = sum_c w[o,c]*x[b,c,n] + bias[o]
__global__ void k_lin_in(const float* __restrict__ x, const float* __restrict__ w,
                         const float* __restrict__ bias, float* __restrict__ f0) {
    int t = blockIdx.x * blockDim.x + threadIdx.x;
    if (t >= B * N0) return;
    int b = t / N0, n = t % N0;
    float x0 = x[(b*3+0)*N0 + n];
    float x1 = x[(b*3+1)*N0 + n];
    float x2 = x[(b*3+2)*N0 + n];
#pragma unroll
    for (int o = 0; o < 8; o++) {
        float v = w[o*3+0]*x0 + w[o*3+1]*x1 + w[o*3+2]*x2 + bias[o];
        f0[(b*8+o)*N0 + n] = v;
    }
}

// KNN: for each query, top-16 smallest (sqq + sqk - 2*inner) among NK keys.
// Sorted top-16 maintained with rank-based PARALLEL insertion (no dependent
// compare-swap chain). Strict '<' on entry + stable shift => lowest-index
// wins ties, matching jax.lax.top_k.
template<int NK>
__global__ void k_knn(const float* __restrict__ cq, const float* __restrict__ ck,
                      int Nq, int* __restrict__ idx_out) {
    __shared__ float4 skey[NK];
    int b = blockIdx.y;
    const float* ckb = ck + (size_t)b*3*NK;
    for (int j = threadIdx.x; j < NK; j += blockDim.x) {
        float kx = ckb[j], ky = ckb[NK + j], kz = ckb[2*NK + j];
        skey[j] = make_float4(kx, ky, kz, kx*kx + ky*ky + kz*kz);
    }
    __syncthreads();
    int q = blockIdx.x * blockDim.x + threadIdx.x;
    if (q >= Nq) return;
    const float* cqb = cq + (size_t)b*3*Nq;
    float qx = cqb[q], qy = cqb[Nq + q], qz = cqb[2*Nq + q];
    float sqq = qx*qx + qy*qy + qz*qz;

    float bd[KN]; int bi[KN];
    // seed with first KN keys, then sort (insertion sort on 16, one-time cost)
#pragma unroll
    for (int i = 0; i < KN; i++) {
        float4 kk = skey[i];
        float inner = qx*kk.x + qy*kk.y + qz*kk.z;
        bd[i] = fmaf(-2.0f, inner, sqq + kk.w);
        bi[i] = i;
    }
#pragma unroll
    for (int a = 1; a < KN; a++) {
#pragma unroll
        for (int i = KN-1; i >= 1; --i) {
            // stable bubble: only swap when strictly smaller (preserves index order on ties)
            bool sw = (bd[i] < bd[i-1]);
            float tv = sw ? bd[i-1] : bd[i];
            float tu = sw ? bd[i]   : bd[i-1];
            int   ti = sw ? bi[i-1] : bi[i];
            int   tj = sw ? bi[i]   : bi[i-1];
            bd[i] = tv; bd[i-1] = tu; bi[i] = ti; bi[i-1] = tj;
        }
    }

    for (int j = KN; j < NK; j++) {
        float4 kk = skey[j];
        float inner = qx*kk.x + qy*kk.y + qz*kk.z;
        float d = fmaf(-2.0f, inner, sqq + kk.w);
        if (d < bd[KN-1]) {
            // rank: number of entries <= d (ties keep existing, all existing j' < j)
            int r = 0;
#pragma unroll
            for (int i = 0; i < KN; i++) r += (bd[i] <= d) ? 1 : 0;
            // parallel shift right of entries at positions >= r (reads all old values)
#pragma unroll
            for (int i = KN-1; i >= 1; --i) {
                bool sh = (i > r);
                bd[i] = sh ? bd[i-1] : bd[i];
                bi[i] = sh ? bi[i-1] : bi[i];
            }
#pragma unroll
            for (int i = 0; i < KN; i++) {
                if (i == r) { bd[i] = d; bi[i] = j; }
            }
        }
    }
    int* ob = idx_out + ((size_t)b*Nq + q) * KN;
#pragma unroll
    for (int i = 0; i < KN; i++) ob[i] = bi[i];
}

// Furthest point sampling. One block per batch. Matches jax scan semantics:
// out[s] = last; dist = min(dist, d(centroid=last)); last = argmax(dist) (first max).
// Point coords live in registers; reductions via REDUX (reduce_max/min_sync).
template<int N, int S, int BLK>
__global__ void k_fps(const float* __restrict__ coor, int* __restrict__ out) {
    constexpr int PPT = N / BLK;
    constexpr int NW  = BLK / 32;
    __shared__ float sx[N], sy[N], sz[N];
    __shared__ unsigned int svv[NW], svi[NW];
    __shared__ int sres;
    int b = blockIdx.x, t = threadIdx.x;
    int lane = t & 31, w = t >> 5;
    const float* cb = coor + (size_t)b*3*N;

    float px[PPT], py[PPT], pz[PPT], dist[PPT];
#pragma unroll
    for (int p = 0; p < PPT; p++) {
        int i = t + p * BLK;
        float vx = cb[i], vy = cb[N + i], vz = cb[2*N + i];
        px[p] = vx; py[p] = vy; pz[p] = vz;
        sx[i] = vx; sy[i] = vy; sz[i] = vz;
        dist[p] = 1e10f;
    }
    __syncthreads();

    int last = 0;
    for (int s = 0; s < S; s++) {
        float cx = sx[last], cy = sy[last], cz = sz[last];
        float bv = -1.0f; int bidx = 0;
#pragma unroll
        for (int p = 0; p < PPT; p++) {
            float dx = px[p]-cx, dy = py[p]-cy, dz = pz[p]-cz;
            float d = dx*dx + dy*dy + dz*dz;
            float nd = fminf(dist[p], d);
            dist[p] = nd;
            if (nd > bv) { bv = nd; bidx = t + p * BLK; }   // ascending idx => first-max
        }
        // dist >= 0 so float bits order == unsigned order
        unsigned bits = __float_as_uint(bv < 0.f ? 0.f : bv);
        unsigned m  = __reduce_max_sync(0xffffffffu, bits);
        unsigned ci = (bits == m) ? (unsigned)bidx : 0xffffffffu;
        unsigned mi = __reduce_min_sync(0xffffffffu, ci);
        if (lane == 0) { svv[w] = m; svi[w] = mi; }
        __syncthreads();
        if (t == 0) {
            out[(size_t)b*S + s] = last;
            unsigned bm = svv[0], bj = svi[0];
#pragma unroll
            for (int i2 = 1; i2 < NW; i2++) {
                unsigned vv = svv[i2], ii = svi[i2];
                if (vv > bm || (vv == bm && ii < bj)) { bm = vv; bj = ii; }
            }
            sres = (int)bj;
        }
        __syncthreads();
        last = sres;
    }
}

// gather: dst[b,c,s] = src[b,c,idx[b,s]]
__global__ void k_gather(const float* __restrict__ src, const int* __restrict__ idx,
                         int C, int Nin, int S, float* __restrict__ dst) {
    int b = blockIdx.y;
    int t = blockIdx.x * blockDim.x + threadIdx.x;
    if (t >= C * S) return;
    int c = t / S, s = t % S;
    dst[((size_t)b*C + c)*S + s] = src[((size_t)b*C + c)*Nin + idx[(size_t)b*S + s]];
}

// GEMM: g[b,j,o] = sum_c wsel[o,c] * f[b,c,j]
// DIFF=false: wsel = w[o, c]          (key-part, first C columns of (Cout,2C))
// DIFF=true : wsel = w[o, C+c] - w[o, c]
template<int C, int Cout, bool DIFF>
__global__ void k_gemm(const float* __restrict__ f, const float* __restrict__ w,
                       int Nk, float* __restrict__ g) {
    constexpr int OC = Cout / 4;
    __shared__ float ws[C * Cout];    // transposed: ws[c*Cout + o]
    int b = blockIdx.y;
    for (int i = threadIdx.x; i < C * Cout; i += blockDim.x) {
        int c = i / Cout, o = i % Cout;
        float v = w[o*2*C + c];
        if (DIFF) v = w[o*2*C + C + c] - v;
        ws[c*Cout + o] = v;
    }
    __syncthreads();
    int t = blockIdx.x * blockDim.x + threadIdx.x;
    int j = t / OC, oc = t % OC;
    if (j >= Nk) return;
    const float* fb = f + (size_t)b*C*Nk;
    float a0 = 0.f, a1 = 0.f, a2 = 0.f, a3 = 0.f;
#pragma unroll
    for (int c = 0; c < C; c++) {
        float fv = fb[(size_t)c*Nk + j];
        float4 wv = *(const float4*)&ws[c*Cout + oc*4];
        a0 += fv * wv.x; a1 += fv * wv.y; a2 += fv * wv.z; a3 += fv * wv.w;
    }
    *(float4*)&g[((size_t)b*Nk + j)*Cout + oc*4] = make_float4(a0, a1, a2, a3);
}

// fused: y[o,n,k] = g[j(n,k),o] + h[n,o]; track max_k/min_k per (n,o),
// and accumulate group sum/sumsq (GroupNorm stats over (C/4, Nq, K) per batch/group).
template<int Cout>
__global__ void k_stats_max(const float* __restrict__ g, const float* __restrict__ h,
                            const int* __restrict__ idx, int Nq, int Nk,
                            float* __restrict__ mx, float* __restrict__ mn,
                            double* __restrict__ stats) {
    constexpr int OC = Cout / 4;
    __shared__ float ssum[4], ssq[4];
    int b = blockIdx.y;
    if (threadIdx.x < 4) { ssum[threadIdx.x] = 0.f; ssq[threadIdx.x] = 0.f; }
    __syncthreads();
    int t = blockIdx.x * blockDim.x + threadIdx.x;
    int n = t / OC, oc = t % OC;
    float s = 0.f, ss = 0.f;
    int grp = 0;
    if (n < Nq) {
        grp = (oc * 16) / Cout;   // 4 channels per thread, Cout/4 channels per group
        const int* ib = idx + ((size_t)b*Nq + n) * KN;
        float4 hv = *(const float4*)&h[((size_t)b*Nq + n)*Cout + oc*4];
        float4 m4 = make_float4(-3.4e38f, -3.4e38f, -3.4e38f, -3.4e38f);
        float4 n4 = make_float4( 3.4e38f,  3.4e38f,  3.4e38f,  3.4e38f);
#pragma unroll
        for (int k = 0; k < KN; k++) {
            int j = ib[k];
            float4 gv = *(const float4*)&g[((size_t)b*Nk + j)*Cout + oc*4];
            float y0 = gv.x + hv.x, y1 = gv.y + hv.y, y2 = gv.z + hv.z, y3 = gv.w + hv.w;
            m4.x = fmaxf(m4.x, y0); m4.y = fmaxf(m4.y, y1);
            m4.z = fmaxf(m4.z, y2); m4.w = fmaxf(m4.w, y3);
            n4.x = fminf(n4.x, y0); n4.y = fminf(n4.y, y1);
            n4.z = fminf(n4.z, y2); n4.w = fminf(n4.w, y3);
            s  += (y0 + y1) + (y2 + y3);
            ss += (y0*y0 + y1*y1) + (y2*y2 + y3*y3);
        }
        *(float4*)&mx[((size_t)b*Nq + n)*Cout + oc*4] = m4;
        *(float4*)&mn[((size_t)b*Nq + n)*Cout + oc*4] = n4;
    }
    atomicAdd(&ssum[grp], s);
    atomicAdd(&ssq[grp], ss);
    __syncthreads();
    if (threadIdx.x < 4) {
        atomicAdd(&stats[((size_t)b*4 + threadIdx.x)*2 + 0], (double)ssum[threadIdx.x]);
        atomicAdd(&stats[((size_t)b*4 + threadIdx.x)*2 + 1], (double)ssq[threadIdx.x]);
    }
}

// finalize: f_out[b,o,n] = lrelu((sel - mean)*rstd*gamma[o] + beta[o]),
// sel = max if gamma>=0 else min (monotone-commuted through norm+lrelu).
template<int Cout>
__global__ void k_finalize(const float* __restrict__ mx, const float* __restrict__ mn,
                           const double* __restrict__ stats,
                           const float* __restrict__ gamma, const float* __restrict__ beta,
                           int Nq, float* __restrict__ fout) {
    int b = blockIdx.y;
    int t = blockIdx.x * blockDim.x + threadIdx.x;
    if (t >= Cout * Nq) return;
    int o = t / Nq, n = t % Nq;
    int grp = o / (Cout / 4);
    double cnt = (double)(Cout / 4) * (double)Nq * (double)KN;
    double su = stats[((size_t)b*4 + grp)*2 + 0];
    double sq = stats[((size_t)b*4 + grp)*2 + 1];
    double m  = su / cnt;
    double vr = sq / cnt - m * m;
    float mean = (float)m;
    float rstd = rsqrtf((float)vr + 1e-5f);
    float ga = gamma[o], be = beta[o];
    float sel = (ga >= 0.f) ? mx[((size_t)b*Nq + n)*Cout + o]
                            : mn[((size_t)b*Nq + n)*Cout + o];
    float v = (sel - mean) * rstd * ga + be;
    fout[((size_t)b*Cout + o)*Nq + n] = (v >= 0.f) ? v : 0.2f * v;
}

// ---------------- launch ----------------
extern "C" void kernel_launch(void* const* d_in, const int* in_sizes, int n_in,
                              void* d_out, int out_size) {
    const float* x    = (const float*)d_in[0];
    const float* w_in = (const float*)d_in[1];
    const float* b_in = (const float*)d_in[2];
    const float* w1 = (const float*)d_in[3];
    const float* g1p = (const float*)d_in[4];
    const float* b1p = (const float*)d_in[5];
    const float* w2 = (const float*)d_in[6];
    const float* g2p = (const float*)d_in[7];
    const float* b2p = (const float*)d_in[8];
    const float* w3 = (const float*)d_in[9];
    const float* g3p = (const float*)d_in[10];
    const float* b3p = (const float*)d_in[11];
    const float* w4 = (const float*)d_in[12];
    const float* g4p = (const float*)d_in[13];
    const float* b4p = (const float*)d_in[14];

    float*  fb;  cudaGetSymbolAddress((void**)&fb,  d_fbuf);
    int*    ib;  cudaGetSymbolAddress((void**)&ib,  d_ibuf);
    double* st;  cudaGetSymbolAddress((void**)&st,  d_statsbuf);
    float*  out = (float*)d_out;

    float* f0  = fb + OFF_F0;
    float* g1  = fb + OFF_G1;  float* h1 = fb + OFF_H1;
    float* m1  = fb + OFF_M1;  float* mn1 = fb + OFF_MN1; float* f1 = fb + OFF_F1;
    float* cq1 = fb + OFF_CQ1; float* fq1 = fb + OFF_FQ1;
    float* g2  = fb + OFF_G2;  float* h2 = fb + OFF_H2;
    float* m2  = fb + OFF_M2;  float* mn2 = fb + OFF_MN2; float* f2 = fb + OFF_F2;
    float* g3  = fb + OFF_G3;  float* h3 = fb + OFF_H3;
    float* m3  = fb + OFF_M3;  float* mn3 = fb + OFF_MN3; float* f3 = fb + OFF_F3;
    float* fq3 = fb + OFF_FQ3;
    float* g4  = fb + OFF_G4;  float* h4 = fb + OFF_H4;
    float* m4  = fb + OFF_M4;  float* mn4 = fb + OFF_MN4;

    int* idx1 = ib + IOFF_IDX1; int* fps1 = ib + IOFF_FPS1;
    int* idx2 = ib + IOFF_IDX2; int* idx3 = ib + IOFF_IDX3;
    int* fps2 = ib + IOFF_FPS2; int* idx4 = ib + IOFF_IDX4;

    double* st1 = st + 0 * B * 8;
    double* st2 = st + 1 * B * 8;
    double* st3 = st + 2 * B * 8;
    double* st4 = st + 3 * B * 8;

    float* out_coor = out;                 // (B,3,128)
    float* out_f    = out + B * 3 * N2;    // (B,128,128)

    k_zero_stats<<<CDIV(4*B*8, 256), 256>>>(st, 4*B*8);
    k_lin_in<<<CDIV(B*N0, 256), 256>>>(x, w_in, b_in, f0);

    // stage 1 on full cloud
    k_knn<N0><<<dim3(CDIV(N0,256), B), 256>>>(x, x, N0, idx1);
    k_fps<N0, N1, 256><<<B, 256>>>(x, fps1);

    k_gemm<8, 32, false><<<dim3(CDIV(N0*8, 128), B), 128>>>(f0, w1, N0, g1);
    k_gemm<8, 32, true ><<<dim3(CDIV(N0*8, 128), B), 128>>>(f0, w1, N0, h1);
    k_stats_max<32><<<dim3(CDIV(N0*8, 128), B), 128>>>(g1, h1, idx1, N0, N0, m1, mn1, st1);
    k_finalize<32><<<dim3(CDIV(32*N0, 256), B), 256>>>(m1, mn1, st1, g1p, b1p, N0, f1);

    // sample 512
    k_gather<<<dim3(CDIV(3*N1, 256), B), 256>>>(x,  fps1, 3,  N0, N1, cq1);
    k_gather<<<dim3(CDIV(32*N1, 256), B), 256>>>(f1, fps1, 32, N0, N1, fq1);
    k_fps<N1, N2, 128><<<B, 128>>>(cq1, fps2);

    // stage 2: queries cq1 (512), keys x (2048)
    k_knn<N0><<<dim3(CDIV(N1,256), B), 256>>>(cq1, x, N1, idx2);
    k_gemm<32, 64, false><<<dim3(CDIV(N0*16, 128), B), 128>>>(f1,  w2, N0, g2);
    k_gemm<32, 64, true ><<<dim3(CDIV(N1*16, 128), B), 128>>>(fq1, w2, N1, h2);
    k_stats_max<64><<<dim3(CDIV(N1*16, 128), B), 128>>>(g2, h2, idx2, N1, N0, m2, mn2, st2);
    k_finalize<64><<<dim3(CDIV(64*N1, 256), B), 256>>>(m2, mn2, st2, g2p, b2p, N1, f2);

    // stage 3: queries = keys = cq1 (512)
    k_knn<N1><<<dim3(CDIV(N1,256), B), 256>>>(cq1, cq1, N1, idx3);
    k_gemm<64, 64, false><<<dim3(CDIV(N1*16, 128), B), 128>>>(f2, w3, N1, g3);
    k_gemm<64, 64, true ><<<dim3(CDIV(N1*16, 128), B), 128>>>(f2, w3, N1, h3);
    k_stats_max<64><<<dim3(CDIV(N1*16, 128), B), 128>>>(g3, h3, idx3, N1, N1, m3, mn3, st3);
    k_finalize<64><<<dim3(CDIV(64*N1, 256), B), 256>>>(m3, mn3, st3, g3p, b3p, N1, f3);

    // sample 128
    k_gather<<<dim3(CDIV(3*N2, 256), B), 256>>>(cq1, fps2, 3,  N1, N2, out_coor);
    k_gather<<<dim3(CDIV(64*N2, 256), B), 256>>>(f3,  fps2, 64, N1, N2, fq3);

    // stage 4: queries out_coor (128), keys cq1 (512)
    k_knn<N1><<<dim3(CDIV(N2,256), B), 256>>>(out_coor, cq1, N2, idx4);
    k_gemm<64, 128, false><<<dim3(CDIV(N1*32, 128), B), 128>>>(f3,  w4, N1, g4);
    k_gemm<64, 128, true ><<<dim3(CDIV(N2*32, 128), B), 128>>>(fq3, w4, N2, h4);
    k_stats_max<128><<<dim3(CDIV(N2*32, 128), B), 128>>>(g4, h4, idx4, N2, N1, m4, mn4, st4);
    k_finalize<128><<<dim3(CDIV(128*N2, 256), B), 256>>>(m4, mn4, st4, g4p, b4p, N2, out_f);
}

// round 4
// speedup vs baseline: 1.4893x; 1.4893x over previous
#include <cuda_runtime.h>
#include <math.h>

#define CDIV(a,b) (((a)+(b)-1)/(b))

static constexpr int B  = 32;
static constexpr int KN = 16;     // neighborhood size
static constexpr int N0 = 2048, N1 = 512, N2 = 128;

// ---------------- scratch (device globals; no allocation allowed) ----------------
static constexpr size_t OFF_F0  = 0;                                  // B*8*N0
static constexpr size_t OFF_G1  = OFF_F0  + (size_t)B*8*N0;           // B*N0*32
static constexpr size_t OFF_H1  = OFF_G1  + (size_t)B*N0*32;          // B*N0*32
static constexpr size_t OFF_M1  = OFF_H1  + (size_t)B*N0*32;
static constexpr size_t OFF_MN1 = OFF_M1  + (size_t)B*N0*32;
static constexpr size_t OFF_F1  = OFF_MN1 + (size_t)B*N0*32;          // B*32*N0
static constexpr size_t OFF_CQ1 = OFF_F1  + (size_t)B*32*N0;          // B*3*N1
static constexpr size_t OFF_FQ1 = OFF_CQ1 + (size_t)B*3*N1;           // B*32*N1
static constexpr size_t OFF_G2  = OFF_FQ1 + (size_t)B*32*N1;          // B*N0*64
static constexpr size_t OFF_H2  = OFF_G2  + (size_t)B*N0*64;          // B*N1*64
static constexpr size_t OFF_M2  = OFF_H2  + (size_t)B*N1*64;
static constexpr size_t OFF_MN2 = OFF_M2  + (size_t)B*N1*64;
static constexpr size_t OFF_F2  = OFF_MN2 + (size_t)B*N1*64;          // B*64*N1
static constexpr size_t OFF_G3  = OFF_F2  + (size_t)B*64*N1;          // B*N1*64
static constexpr size_t OFF_H3  = OFF_G3  + (size_t)B*N1*64;
static constexpr size_t OFF_M3  = OFF_H3  + (size_t)B*N1*64;
static constexpr size_t OFF_MN3 = OFF_M3  + (size_t)B*N1*64;
static constexpr size_t OFF_F3  = OFF_MN3 + (size_t)B*N1*64;          // B*64*N1
static constexpr size_t OFF_FQ3 = OFF_F3  + (size_t)B*64*N1;          // B*64*N2
static constexpr size_t OFF_G4  = OFF_FQ3 + (size_t)B*64*N2;          // B*N1*128
static constexpr size_t OFF_H4  = OFF_G4  + (size_t)B*N1*128;         // B*N2*128
static constexpr size_t OFF_M4  = OFF_H4  + (size_t)B*N2*128;
static constexpr size_t OFF_MN4 = OFF_M4  + (size_t)B*N2*128;
static constexpr size_t FBUF_TOTAL = OFF_MN4 + (size_t)B*N2*128;

__device__ float d_fbuf[FBUF_TOTAL];

static constexpr size_t IOFF_IDX1 = 0;                                // B*N0*KN
static constexpr size_t IOFF_FPS1 = IOFF_IDX1 + (size_t)B*N0*KN;      // B*N1
static constexpr size_t IOFF_IDX2 = IOFF_FPS1 + (size_t)B*N1;         // B*N1*KN
static constexpr size_t IOFF_IDX3 = IOFF_IDX2 + (size_t)B*N1*KN;      // B*N1*KN
static constexpr size_t IOFF_FPS2 = IOFF_IDX3 + (size_t)B*N1*KN;      // B*N2
static constexpr size_t IOFF_IDX4 = IOFF_FPS2 + (size_t)B*N2;         // B*N2*KN
static constexpr size_t IBUF_TOTAL = IOFF_IDX4 + (size_t)B*N2*KN;

__device__ int d_ibuf[IBUF_TOTAL];
__device__ double d_statsbuf[4 * B * 4 * 2];   // [layer][b][group][{sum,sumsq}]

// ---------------- device helpers ----------------

// KNN body (R2-proven insertion chain). 256 threads. Uses smem skey (float4*).
// Strict '<' on entry keeps lowest index on ties, matching jax.lax.top_k.
__device__ __forceinline__ void dev_knn(int NK, const float* __restrict__ cq,
                                        const float* __restrict__ ck,
                                        int Nq, int* __restrict__ idx_out,
                                        int bq, int b, char* sraw) {
    float4* skey = (float4*)sraw;
    const float* ckb = ck + (size_t)b*3*NK;
    for (int j = threadIdx.x; j < NK; j += 256) {
        float kx = ckb[j], ky = ckb[NK + j], kz = ckb[2*NK + j];
        skey[j] = make_float4(kx, ky, kz, kx*kx + ky*ky + kz*kz);
    }
    __syncthreads();
    int q = bq * 256 + threadIdx.x;
    if (q >= Nq) return;
    const float* cqb = cq + (size_t)b*3*Nq;
    float qx = cqb[q], qy = cqb[Nq + q], qz = cqb[2*Nq + q];
    float sqq = qx*qx + qy*qy + qz*qz;

    float bd[KN]; int bi[KN];
#pragma unroll
    for (int i = 0; i < KN; i++) { bd[i] = 3.4e38f; bi[i] = 0; }

    for (int j = 0; j < NK; j++) {
        float4 kk = skey[j];
        float inner = qx*kk.x + qy*kk.y + qz*kk.z;
        float d = sqq + kk.w - 2.0f*inner;
        if (d < bd[KN-1]) {
            bd[KN-1] = d; bi[KN-1] = j;
#pragma unroll
            for (int i = KN-1; i > 0; --i) {
                if (bd[i] < bd[i-1]) {
                    float tv = bd[i]; bd[i] = bd[i-1]; bd[i-1] = tv;
                    int   ti = bi[i]; bi[i] = bi[i-1]; bi[i-1] = ti;
                }
            }
        }
    }
    int* ob = idx_out + ((size_t)b*Nq + q) * KN;
#pragma unroll
    for (int i = 0; i < KN; i++) ob[i] = bi[i];
}

// FPS body: 256 threads, ONE barrier per iteration.
// phase1: local best -> per-warp REDUX -> lane0 store to double-buffered slots
// barrier
// phase2: ALL threads merge the 8 warp results redundantly in registers.
// Matches jnp.argmax first-max semantics (max dist, tie -> min index).
template<int N, int S>
__device__ __forceinline__ void dev_fps(const float* __restrict__ coor,
                                        int* __restrict__ out, int b, char* sraw) {
    constexpr int BLK = 256, PPT = N / BLK, NW = BLK / 32;
    float* sx = (float*)sraw;
    float* sy = sx + N;
    float* sz = sy + N;
    unsigned* svv = (unsigned*)(sz + N);   // [2][NW]
    unsigned* svi = svv + 2*NW;            // [2][NW]
    int t = threadIdx.x, lane = t & 31, w = t >> 5;
    const float* cb = coor + (size_t)b*3*N;

    float px[PPT], py[PPT], pz[PPT], dist[PPT];
#pragma unroll
    for (int p = 0; p < PPT; p++) {
        int i = t + p * BLK;
        float vx = cb[i], vy = cb[N + i], vz = cb[2*N + i];
        px[p] = vx; py[p] = vy; pz[p] = vz;
        sx[i] = vx; sy[i] = vy; sz[i] = vz;
        dist[p] = 1e10f;
    }
    __syncthreads();

    int last = 0;
    for (int s = 0; s < S; s++) {
        if (t == 0) out[(size_t)b*S + s] = last;
        float cx = sx[last], cy = sy[last], cz = sz[last];
        float bv = -1.0f; int bidx = 0;
#pragma unroll
        for (int p = 0; p < PPT; p++) {
            float dx = px[p]-cx, dy = py[p]-cy, dz = pz[p]-cz;
            float d = dx*dx + dy*dy + dz*dz;
            float nd = fminf(dist[p], d);
            dist[p] = nd;
            if (nd > bv) { bv = nd; bidx = t + p * BLK; }   // ascending idx => first-max
        }
        unsigned bits = __float_as_uint(fmaxf(bv, 0.0f));   // dist>=0: bits order == value order
        unsigned m  = __reduce_max_sync(0xffffffffu, bits);
        unsigned ci = (bits == m) ? (unsigned)bidx : 0xffffffffu;
        unsigned mi = __reduce_min_sync(0xffffffffu, ci);
        int buf = (s & 1) * NW;
        if (lane == 0) { svv[buf + w] = m; svi[buf + w] = mi; }
        __syncthreads();
        unsigned bm = svv[buf + 0], bj = svi[buf + 0];
#pragma unroll
        for (int i2 = 1; i2 < NW; i2++) {
            unsigned vv = svv[buf + i2], ii = svi[buf + i2];
            if (vv > bm || (vv == bm && ii < bj)) { bm = vv; bj = ii; }
        }
        last = (int)bj;
    }
}

// ---------------- kernels ----------------

__global__ void k_zero_stats(double* p, int n) {
    int t = blockIdx.x * blockDim.x + threadIdx.x;
    if (t < n) p[t] = 0.0;
}

// f0[b,o,n] = sum_c w[o,c]*x[b,c,n] + bias[o]
__global__ void k_lin_in(const float* __restrict__ x, const float* __restrict__ w,
                         const float* __restrict__ bias, float* __restrict__ f0) {
    int t = blockIdx.x * blockDim.x + threadIdx.x;
    if (t >= B * N0) return;
    int b = t / N0, n = t % N0;
    float x0 = x[(b*3+0)*N0 + n];
    float x1 = x[(b*3+1)*N0 + n];
    float x2 = x[(b*3+2)*N0 + n];
#pragma unroll
    for (int o = 0; o < 8; o++) {
        float v = w[o*3+0]*x0 + w[o*3+1]*x1 + w[o*3+2]*x2 + bias[o];
        f0[(b*8+o)*N0 + n] = v;
    }
}

// megaA: blocks [0,32) -> fps1 (N0->N1); blocks [32,288) -> knn1 (2048q x 2048k per batch)
__global__ __launch_bounds__(256) void k_megaA(const float* __restrict__ x,
                                               int* __restrict__ fps1,
                                               int* __restrict__ idx1) {
    __shared__ __align__(16) char sraw[33792];
    int bid = blockIdx.x;
    if (bid < 32) {
        dev_fps<N0, N1>(x, fps1, bid, sraw);
    } else {
        int r = bid - 32;
        dev_knn(N0, x, x, N0, idx1, r & 7, r >> 3, sraw);
    }
}

// megaB: blocks [0,32) -> fps2 (cq1: N1->N2); [32,96) -> knn2 (512q x 2048k);
//        [96,160) -> knn3 (512q x 512k).
__global__ __launch_bounds__(256) void k_megaB(const float* __restrict__ cq1,
                                               const float* __restrict__ x,
                                               int* __restrict__ fps2,
                                               int* __restrict__ idx2,
                                               int* __restrict__ idx3) {
    __shared__ __align__(16) char sraw[33792];
    int bid = blockIdx.x;
    if (bid < 32) {
        dev_fps<N1, N2>(cq1, fps2, bid, sraw);
    } else if (bid < 96) {
        int r = bid - 32;
        dev_knn(N0, cq1, x, N1, idx2, r & 1, r >> 1, sraw);
    } else {
        int r = bid - 96;
        dev_knn(N1, cq1, cq1, N1, idx3, r & 1, r >> 1, sraw);
    }
}

// standalone knn (stage 4)
template<int NK>
__global__ __launch_bounds__(256) void k_knn(const float* __restrict__ cq,
                                             const float* __restrict__ ck,
                                             int Nq, int* __restrict__ idx_out) {
    __shared__ __align__(16) char sraw[NK * 16];
    dev_knn(NK, cq, ck, Nq, idx_out, blockIdx.x, blockIdx.y, sraw);
}

// gather: dst[b,c,s] = src[b,c,idx[b,s]]
__global__ void k_gather(const float* __restrict__ src, const int* __restrict__ idx,
                         int C, int Nin, int S, float* __restrict__ dst) {
    int b = blockIdx.y;
    int t = blockIdx.x * blockDim.x + threadIdx.x;
    if (t >= C * S) return;
    int c = t / S, s = t % S;
    dst[((size_t)b*C + c)*S + s] = src[((size_t)b*C + c)*Nin + idx[(size_t)b*S + s]];
}

// single-input GEMM: g[b,j,o] = sum_c wsel[o,c] * f[b,c,j]
template<int C, int Cout, bool DIFF>
__global__ void k_gemm(const float* __restrict__ f, const float* __restrict__ w,
                       int Nk, float* __restrict__ g) {
    constexpr int OC = Cout / 4;
    __shared__ float ws[C * Cout];
    int b = blockIdx.y;
    for (int i = threadIdx.x; i < C * Cout; i += blockDim.x) {
        int c = i / Cout, o = i % Cout;
        float v = w[o*2*C + c];
        if (DIFF) v = w[o*2*C + C + c] - v;
        ws[c*Cout + o] = v;
    }
    __syncthreads();
    int t = blockIdx.x * blockDim.x + threadIdx.x;
    int j = t / OC, oc = t % OC;
    if (j >= Nk) return;
    const float* fb = f + (size_t)b*C*Nk;
    float a0 = 0.f, a1 = 0.f, a2 = 0.f, a3 = 0.f;
#pragma unroll
    for (int c = 0; c < C; c++) {
        float fv = fb[(size_t)c*Nk + j];
        float4 wv = *(const float4*)&ws[c*Cout + oc*4];
        a0 += fv * wv.x; a1 += fv * wv.y; a2 += fv * wv.z; a3 += fv * wv.w;
    }
    *(float4*)&g[((size_t)b*Nk + j)*Cout + oc*4] = make_float4(a0, a1, a2, a3);
}

// dual-output GEMM (same input feeds both g and h): one read of f.
template<int C, int Cout>
__global__ void k_gemm2(const float* __restrict__ f, const float* __restrict__ w,
                        int Nk, float* __restrict__ g, float* __restrict__ h) {
    constexpr int OC = Cout / 4;
    __shared__ float ws[2 * C * Cout];
    int b = blockIdx.y;
    for (int i = threadIdx.x; i < C * Cout; i += blockDim.x) {
        int c = i / Cout, o = i % Cout;
        float lo = w[o*2*C + c];
        float hi = w[o*2*C + C + c];
        ws[(2*c)*Cout + o]   = lo;
        ws[(2*c+1)*Cout + o] = hi - lo;
    }
    __syncthreads();
    int t = blockIdx.x * blockDim.x + threadIdx.x;
    int j = t / OC, oc = t % OC;
    if (j >= Nk) return;
    const float* fb = f + (size_t)b*C*Nk;
    float g0=0.f,g1=0.f,g2=0.f,g3=0.f, h0=0.f,h1=0.f,h2=0.f,h3=0.f;
#pragma unroll
    for (int c = 0; c < C; c++) {
        float fv = fb[(size_t)c*Nk + j];
        float4 wl = *(const float4*)&ws[(2*c)*Cout + oc*4];
        float4 wd = *(const float4*)&ws[(2*c+1)*Cout + oc*4];
        g0 += fv*wl.x; g1 += fv*wl.y; g2 += fv*wl.z; g3 += fv*wl.w;
        h0 += fv*wd.x; h1 += fv*wd.y; h2 += fv*wd.z; h3 += fv*wd.w;
    }
    size_t o4 = ((size_t)b*Nk + j)*Cout + oc*4;
    *(float4*)&g[o4] = make_float4(g0,g1,g2,g3);
    *(float4*)&h[o4] = make_float4(h0,h1,h2,h3);
}

// fused: y[o,n,k] = g[j(n,k),o] + h[n,o]; track max_k/min_k per (n,o),
// and accumulate group sum/sumsq.
template<int Cout>
__global__ void k_stats_max(const float* __restrict__ g, const float* __restrict__ h,
                            const int* __restrict__ idx, int Nq, int Nk,
                            float* __restrict__ mx, float* __restrict__ mn,
                            double* __restrict__ stats) {
    constexpr int OC = Cout / 4;
    __shared__ float ssum[4], ssq[4];
    int b = blockIdx.y;
    if (threadIdx.x < 4) { ssum[threadIdx.x] = 0.f; ssq[threadIdx.x] = 0.f; }
    __syncthreads();
    int t = blockIdx.x * blockDim.x + threadIdx.x;
    int n = t / OC, oc = t % OC;
    float s = 0.f, ss = 0.f;
    int grp = 0;
    if (n < Nq) {
        grp = (oc * 16) / Cout;
        const int* ib = idx + ((size_t)b*Nq + n) * KN;
        float4 hv = *(const float4*)&h[((size_t)b*Nq + n)*Cout + oc*4];
        float4 m4 = make_float4(-3.4e38f, -3.4e38f, -3.4e38f, -3.4e38f);
        float4 n4 = make_float4( 3.4e38f,  3.4e38f,  3.4e38f,  3.4e38f);
#pragma unroll
        for (int k = 0; k < KN; k++) {
            int j = ib[k];
            float4 gv = *(const float4*)&g[((size_t)b*Nk + j)*Cout + oc*4];
            float y0 = gv.x + hv.x, y1 = gv.y + hv.y, y2 = gv.z + hv.z, y3 = gv.w + hv.w;
            m4.x = fmaxf(m4.x, y0); m4.y = fmaxf(m4.y, y1);
            m4.z = fmaxf(m4.z, y2); m4.w = fmaxf(m4.w, y3);
            n4.x = fminf(n4.x, y0); n4.y = fminf(n4.y, y1);
            n4.z = fminf(n4.z, y2); n4.w = fminf(n4.w, y3);
            s  += (y0 + y1) + (y2 + y3);
            ss += (y0*y0 + y1*y1) + (y2*y2 + y3*y3);
        }
        *(float4*)&mx[((size_t)b*Nq + n)*Cout + oc*4] = m4;
        *(float4*)&mn[((size_t)b*Nq + n)*Cout + oc*4] = n4;
    }
    atomicAdd(&ssum[grp], s);
    atomicAdd(&ssq[grp], ss);
    __syncthreads();
    if (threadIdx.x < 4) {
        atomicAdd(&stats[((size_t)b*4 + threadIdx.x)*2 + 0], (double)ssum[threadIdx.x]);
        atomicAdd(&stats[((size_t)b*4 + threadIdx.x)*2 + 1], (double)ssq[threadIdx.x]);
    }
}

// finalize: f_out[b,o,n] = lrelu((sel - mean)*rstd*gamma[o] + beta[o]),
// sel = max if gamma>=0 else min (monotone-commuted through norm+lrelu).
template<int Cout>
__global__ void k_finalize(const float* __restrict__ mx, const float* __restrict__ mn,
                           const double* __restrict__ stats,
                           const float* __restrict__ gamma, const float* __restrict__ beta,
                           int Nq, float* __restrict__ fout) {
    int b = blockIdx.y;
    int t = blockIdx.x * blockDim.x + threadIdx.x;
    if (t >= Cout * Nq) return;
    int o = t / Nq, n = t % Nq;
    int grp = o / (Cout / 4);
    double cnt = (double)(Cout / 4) * (double)Nq * (double)KN;
    double su = stats[((size_t)b*4 + grp)*2 + 0];
    double sq = stats[((size_t)b*4 + grp)*2 + 1];
    double m  = su / cnt;
    double vr = sq / cnt - m * m;
    float mean = (float)m;
    float rstd = rsqrtf((float)vr + 1e-5f);
    float ga = gamma[o], be = beta[o];
    float sel = (ga >= 0.f) ? mx[((size_t)b*Nq + n)*Cout + o]
                            : mn[((size_t)b*Nq + n)*Cout + o];
    float v = (sel - mean) * rstd * ga + be;
    fout[((size_t)b*Cout + o)*Nq + n] = (v >= 0.f) ? v : 0.2f * v;
}

// ---------------- launch ----------------
extern "C" void kernel_launch(void* const* d_in, const int* in_sizes, int n_in,
                              void* d_out, int out_size) {
    const float* x    = (const float*)d_in[0];
    const float* w_in = (const float*)d_in[1];
    const float* b_in = (const float*)d_in[2];
    const float* w1 = (const float*)d_in[3];
    const float* g1p = (const float*)d_in[4];
    const float* b1p = (const float*)d_in[5];
    const float* w2 = (const float*)d_in[6];
    const float* g2p = (const float*)d_in[7];
    const float* b2p = (const float*)d_in[8];
    const float* w3 = (const float*)d_in[9];
    const float* g3p = (const float*)d_in[10];
    const float* b3p = (const float*)d_in[11];
    const float* w4 = (const float*)d_in[12];
    const float* g4p = (const float*)d_in[13];
    const float* b4p = (const float*)d_in[14];

    float*  fb;  cudaGetSymbolAddress((void**)&fb,  d_fbuf);
    int*    ib;  cudaGetSymbolAddress((void**)&ib,  d_ibuf);
    double* st;  cudaGetSymbolAddress((void**)&st,  d_statsbuf);
    float*  out = (float*)d_out;

    float* f0  = fb + OFF_F0;
    float* g1  = fb + OFF_G1;  float* h1 = fb + OFF_H1;
    float* m1  = fb + OFF_M1;  float* mn1 = fb + OFF_MN1; float* f1 = fb + OFF_F1;
    float* cq1 = fb + OFF_CQ1; float* fq1 = fb + OFF_FQ1;
    float* g2  = fb + OFF_G2;  float* h2 = fb + OFF_H2;
    float* m2  = fb + OFF_M2;  float* mn2 = fb + OFF_MN2; float* f2 = fb + OFF_F2;
    float* g3  = fb + OFF_G3;  float* h3 = fb + OFF_H3;
    float* m3  = fb + OFF_M3;  float* mn3 = fb + OFF_MN3; float* f3 = fb + OFF_F3;
    float* fq3 = fb + OFF_FQ3;
    float* g4  = fb + OFF_G4;  float* h4 = fb + OFF_H4;
    float* m4  = fb + OFF_M4;  float* mn4 = fb + OFF_MN4;

    int* idx1 = ib + IOFF_IDX1; int* fps1 = ib + IOFF_FPS1;
    int* idx2 = ib + IOFF_IDX2; int* idx3 = ib + IOFF_IDX3;
    int* fps2 = ib + IOFF_FPS2; int* idx4 = ib + IOFF_IDX4;

    double* st1 = st + 0 * B * 8;
    double* st2 = st + 1 * B * 8;
    double* st3 = st + 2 * B * 8;
    double* st4 = st + 3 * B * 8;

    float* out_coor = out;                 // (B,3,128)
    float* out_f    = out + B * 3 * N2;    // (B,128,128)

    k_zero_stats<<<CDIV(4*B*8, 256), 256>>>(st, 4*B*8);
    k_lin_in<<<CDIV(B*N0, 256), 256>>>(x, w_in, b_in, f0);

    // stage 1: fps1 and knn1 run concurrently in one launch
    k_megaA<<<32 + 256, 256>>>(x, fps1, idx1);

    k_gemm2<8, 32><<<dim3(CDIV(N0*8, 256), B), 256>>>(f0, w1, N0, g1, h1);
    k_stats_max<32><<<dim3(CDIV(N0*8, 128), B), 128>>>(g1, h1, idx1, N0, N0, m1, mn1, st1);
    k_finalize<32><<<dim3(CDIV(32*N0, 256), B), 256>>>(m1, mn1, st1, g1p, b1p, N0, f1);

    // sample 512
    k_gather<<<dim3(CDIV(3*N1, 256), B), 256>>>(x,  fps1, 3,  N0, N1, cq1);
    k_gather<<<dim3(CDIV(32*N1, 256), B), 256>>>(f1, fps1, 32, N0, N1, fq1);

    // fps2, knn2, knn3 all depend only on cq1: one launch
    k_megaB<<<32 + 64 + 64, 256>>>(cq1, x, fps2, idx2, idx3);

    // stage 2: queries cq1 (512), keys x (2048)
    k_gemm<32, 64, false><<<dim3(CDIV(N0*16, 128), B), 128>>>(f1,  w2, N0, g2);
    k_gemm<32, 64, true ><<<dim3(CDIV(N1*16, 128), B), 128>>>(fq1, w2, N1, h2);
    k_stats_max<64><<<dim3(CDIV(N1*16, 128), B), 128>>>(g2, h2, idx2, N1, N0, m2, mn2, st2);
    k_finalize<64><<<dim3(CDIV(64*N1, 256), B), 256>>>(m2, mn2, st2, g2p, b2p, N1, f2);

    // stage 3: queries = keys = cq1 (512)
    k_gemm2<64, 64><<<dim3(CDIV(N1*16, 256), B), 256>>>(f2, w3, N1, g3, h3);
    k_stats_max<64><<<dim3(CDIV(N1*16, 128), B), 128>>>(g3, h3, idx3, N1, N1, m3, mn3, st3);
    k_finalize<64><<<dim3(CDIV(64*N1, 256), B), 256>>>(m3, mn3, st3, g3p, b3p, N1, f3);

    // sample 128
    k_gather<<<dim3(CDIV(3*N2, 256), B), 256>>>(cq1, fps2, 3,  N1, N2, out_coor);
    k_gather<<<dim3(CDIV(64*N2, 256), B), 256>>>(f3,  fps2, 64, N1, N2, fq3);

    // stage 4: queries out_coor (128), keys cq1 (512)
    k_knn<N1><<<dim3(1, B), 256>>>(out_coor, cq1, N2, idx4);
    k_gemm<64, 128, false><<<dim3(CDIV(N1*32, 128), B), 128>>>(f3,  w4, N1, g4);
    k_gemm<64, 128, true ><<<dim3(CDIV(N2*32, 128), B), 128>>>(fq3, w4, N2, h4);
    k_stats_max<128><<<dim3(CDIV(N2*32, 128), B), 128>>>(g4, h4, idx4, N2, N1, m4, mn4, st4);
    k_finalize<128><<<dim3(CDIV(128*N2, 256), B), 256>>>(m4, mn4, st4, g4p, b4p, N2, out_f);
}

// round 5
// speedup vs baseline: 1.5462x; 1.0382x over previous
#include <cuda_runtime.h>
#include <math.h>

#define CDIV(a,b) (((a)+(b)-1)/(b))

static constexpr int B  = 32;
static constexpr int KN = 16;     // neighborhood size
static constexpr int N0 = 2048, N1 = 512, N2 = 128;

// ---------------- scratch (device globals; no allocation allowed) ----------------
static constexpr size_t OFF_F0  = 0;                                  // B*8*N0
static constexpr size_t OFF_G1  = OFF_F0  + (size_t)B*8*N0;           // B*N0*32
static constexpr size_t OFF_H1  = OFF_G1  + (size_t)B*N0*32;          // B*N0*32
static constexpr size_t OFF_M1  = OFF_H1  + (size_t)B*N0*32;
static constexpr size_t OFF_MN1 = OFF_M1  + (size_t)B*N0*32;
static constexpr size_t OFF_F1  = OFF_MN1 + (size_t)B*N0*32;          // B*32*N0
static constexpr size_t OFF_CQ1 = OFF_F1  + (size_t)B*32*N0;          // B*3*N1
static constexpr size_t OFF_FQ1 = OFF_CQ1 + (size_t)B*3*N1;           // B*32*N1
static constexpr size_t OFF_G2  = OFF_FQ1 + (size_t)B*32*N1;          // B*N0*64
static constexpr size_t OFF_H2  = OFF_G2  + (size_t)B*N0*64;          // B*N1*64
static constexpr size_t OFF_M2  = OFF_H2  + (size_t)B*N1*64;
static constexpr size_t OFF_MN2 = OFF_M2  + (size_t)B*N1*64;
static constexpr size_t OFF_F2  = OFF_MN2 + (size_t)B*N1*64;          // B*64*N1
static constexpr size_t OFF_G3  = OFF_F2  + (size_t)B*64*N1;          // B*N1*64
static constexpr size_t OFF_H3  = OFF_G3  + (size_t)B*N1*64;
static constexpr size_t OFF_M3  = OFF_H3  + (size_t)B*N1*64;
static constexpr size_t OFF_MN3 = OFF_M3  + (size_t)B*N1*64;
static constexpr size_t OFF_F3  = OFF_MN3 + (size_t)B*N1*64;          // B*64*N1
static constexpr size_t OFF_FQ3 = OFF_F3  + (size_t)B*64*N1;          // B*64*N2
static constexpr size_t OFF_G4  = OFF_FQ3 + (size_t)B*64*N2;          // B*N1*128
static constexpr size_t OFF_H4  = OFF_G4  + (size_t)B*N1*128;         // B*N2*128
static constexpr size_t OFF_M4  = OFF_H4  + (size_t)B*N2*128;
static constexpr size_t OFF_MN4 = OFF_M4  + (size_t)B*N2*128;
static constexpr size_t FBUF_TOTAL = OFF_MN4 + (size_t)B*N2*128;

__device__ float d_fbuf[FBUF_TOTAL];

static constexpr size_t IOFF_IDX1 = 0;                                // B*N0*KN
static constexpr size_t IOFF_FPS1 = IOFF_IDX1 + (size_t)B*N0*KN;      // B*N1
static constexpr size_t IOFF_IDX2 = IOFF_FPS1 + (size_t)B*N1;         // B*N1*KN
static constexpr size_t IOFF_IDX3 = IOFF_IDX2 + (size_t)B*N1*KN;      // B*N1*KN
static constexpr size_t IOFF_FPS2 = IOFF_IDX3 + (size_t)B*N1*KN;      // B*N2
static constexpr size_t IOFF_IDX4 = IOFF_FPS2 + (size_t)B*N2;         // B*N2*KN
static constexpr size_t IBUF_TOTAL = IOFF_IDX4 + (size_t)B*N2*KN;

__device__ int d_ibuf[IBUF_TOTAL];
__device__ double d_statsbuf[4 * B * 4 * 2];   // [layer][b][group][{sum,sumsq}]

// ---------------- device helpers ----------------

// KNN with buffered inserts. 256 threads. Requires Nq % 32 == 0 (whole warps active).
// Hits get appended to a per-thread local buffer (unconditional store, predicated
// count => no branch); sorted top-16 insertion happens only at warp-synchronized
// compaction events, batching the expensive divergent inserts.
// Strict '<' + ascending-j processing keeps lowest index on ties (matches top_k).
__device__ __forceinline__ void dev_knn(int NK, const float* __restrict__ cq,
                                        const float* __restrict__ ck,
                                        int Nq, int* __restrict__ idx_out,
                                        int bq, int b, char* sraw) {
    float4* skey = (float4*)sraw;
    const float* ckb = ck + (size_t)b*3*NK;
    for (int j = threadIdx.x; j < NK; j += 256) {
        float kx = ckb[j], ky = ckb[NK + j], kz = ckb[2*NK + j];
        skey[j] = make_float4(kx, ky, kz, kx*kx + ky*ky + kz*kz);
    }
    __syncthreads();
    int q = bq * 256 + threadIdx.x;
    if (q >= Nq) return;
    const float* cqb = cq + (size_t)b*3*Nq;
    float qx = cqb[q], qy = cqb[Nq + q], qz = cqb[2*Nq + q];
    float sqq = qx*qx + qy*qy + qz*qz;

    float bd[KN]; int bi[KN];
#pragma unroll
    for (int i = 0; i < KN; i++) { bd[i] = 3.4e38f; bi[i] = 0; }

    float bufd[16]; int bufj[16];
    int cnt = 0;

    for (int j0 = 0; j0 < NK; j0 += 8) {
#pragma unroll
        for (int u = 0; u < 8; u++) {
            int j = j0 + u;
            float4 kk = skey[j];
            float inner = qx*kk.x + qy*kk.y + qz*kk.z;
            float d = sqq + kk.w - 2.0f*inner;
            bufd[cnt] = d; bufj[cnt] = j;           // unconditional store
            cnt += (d < bd[KN-1]) ? 1 : 0;          // predicated advance
        }
        if (__any_sync(0xffffffffu, cnt >= 8)) {
            for (int i = 0; i < cnt; i++) {
                float d = bufd[i]; int jj = bufj[i];
                if (d < bd[KN-1]) {
                    bd[KN-1] = d; bi[KN-1] = jj;
#pragma unroll
                    for (int i2 = KN-1; i2 > 0; --i2) {
                        if (bd[i2] < bd[i2-1]) {
                            float tv = bd[i2]; bd[i2] = bd[i2-1]; bd[i2-1] = tv;
                            int   ti = bi[i2]; bi[i2] = bi[i2-1]; bi[i2-1] = ti;
                        }
                    }
                }
            }
            cnt = 0;
        }
    }
    // tail compaction
    for (int i = 0; i < cnt; i++) {
        float d = bufd[i]; int jj = bufj[i];
        if (d < bd[KN-1]) {
            bd[KN-1] = d; bi[KN-1] = jj;
#pragma unroll
            for (int i2 = KN-1; i2 > 0; --i2) {
                if (bd[i2] < bd[i2-1]) {
                    float tv = bd[i2]; bd[i2] = bd[i2-1]; bd[i2-1] = tv;
                    int   ti = bi[i2]; bi[i2] = bi[i2-1]; bi[i2-1] = ti;
                }
            }
        }
    }
    int* ob = idx_out + ((size_t)b*Nq + q) * KN;
#pragma unroll
    for (int i = 0; i < KN; i++) ob[i] = bi[i];
}

// FPS: 256 threads, one barrier per iteration (proven R4 version).
template<int N, int S>
__device__ __forceinline__ void dev_fps(const float* __restrict__ coor,
                                        int* __restrict__ out, int b, char* sraw) {
    constexpr int BLK = 256, PPT = N / BLK, NW = BLK / 32;
    float* sx = (float*)sraw;
    float* sy = sx + N;
    float* sz = sy + N;
    unsigned* svv = (unsigned*)(sz + N);   // [2][NW]
    unsigned* svi = svv + 2*NW;            // [2][NW]
    int t = threadIdx.x, lane = t & 31, w = t >> 5;
    const float* cb = coor + (size_t)b*3*N;

    float px[PPT], py[PPT], pz[PPT], dist[PPT];
#pragma unroll
    for (int p = 0; p < PPT; p++) {
        int i = t + p * BLK;
        float vx = cb[i], vy = cb[N + i], vz = cb[2*N + i];
        px[p] = vx; py[p] = vy; pz[p] = vz;
        sx[i] = vx; sy[i] = vy; sz[i] = vz;
        dist[p] = 1e10f;
    }
    __syncthreads();

    int last = 0;
    for (int s = 0; s < S; s++) {
        if (t == 0) out[(size_t)b*S + s] = last;
        float cx = sx[last], cy = sy[last], cz = sz[last];
        float bv = -1.0f; int bidx = 0;
#pragma unroll
        for (int p = 0; p < PPT; p++) {
            float dx = px[p]-cx, dy = py[p]-cy, dz = pz[p]-cz;
            float d = dx*dx + dy*dy + dz*dz;
            float nd = fminf(dist[p], d);
            dist[p] = nd;
            if (nd > bv) { bv = nd; bidx = t + p * BLK; }   // ascending idx => first-max
        }
        unsigned bits = __float_as_uint(fmaxf(bv, 0.0f));
        unsigned m  = __reduce_max_sync(0xffffffffu, bits);
        unsigned ci = (bits == m) ? (unsigned)bidx : 0xffffffffu;
        unsigned mi = __reduce_min_sync(0xffffffffu, ci);
        int buf = (s & 1) * NW;
        if (lane == 0) { svv[buf + w] = m; svi[buf + w] = mi; }
        __syncthreads();
        unsigned bm = svv[buf + 0], bj = svi[buf + 0];
#pragma unroll
        for (int i2 = 1; i2 < NW; i2++) {
            unsigned vv = svv[buf + i2], ii = svi[buf + i2];
            if (vv > bm || (vv == bm && ii < bj)) { bm = vv; bj = ii; }
        }
        last = (int)bj;
    }
}

// GEMM body, 256 threads: out[b,j,o] = sum_c wsel[o,c]*f[b,c,j]
template<int C, int Cout>
__device__ __forceinline__ void dev_gemm(const float* __restrict__ f,
                                         const float* __restrict__ w,
                                         int Nk, float* __restrict__ out,
                                         bool diff, int bq, int b, float* ws) {
    constexpr int OC = Cout / 4;
    for (int i = threadIdx.x; i < C * Cout; i += 256) {
        int c = i / Cout, o = i % Cout;
        float lo = w[o*2*C + c];
        float hi = w[o*2*C + C + c];
        ws[c*Cout + o] = diff ? (hi - lo) : lo;
    }
    __syncthreads();
    int t = bq * 256 + threadIdx.x;
    int j = t / OC, oc = t % OC;
    if (j >= Nk) return;
    const float* fb = f + (size_t)b*C*Nk;
    float a0 = 0.f, a1 = 0.f, a2 = 0.f, a3 = 0.f;
#pragma unroll
    for (int c = 0; c < C; c++) {
        float fv = fb[(size_t)c*Nk + j];
        float4 wv = *(const float4*)&ws[c*Cout + oc*4];
        a0 += fv * wv.x; a1 += fv * wv.y; a2 += fv * wv.z; a3 += fv * wv.w;
    }
    *(float4*)&out[((size_t)b*Nk + j)*Cout + oc*4] = make_float4(a0, a1, a2, a3);
}

// ---------------- kernels ----------------

// f0 + zero stats (blocks 0..3 also clear the 1024-double stats buffer)
__global__ void k_lin_in(const float* __restrict__ x, const float* __restrict__ w,
                         const float* __restrict__ bias, float* __restrict__ f0,
                         double* __restrict__ st) {
    int t = blockIdx.x * blockDim.x + threadIdx.x;
    if (blockIdx.x < 4) st[blockIdx.x * 256 + threadIdx.x] = 0.0;
    if (t >= B * N0) return;
    int b = t / N0, n = t % N0;
    float x0 = x[(b*3+0)*N0 + n];
    float x1 = x[(b*3+1)*N0 + n];
    float x2 = x[(b*3+2)*N0 + n];
#pragma unroll
    for (int o = 0; o < 8; o++) {
        float v = w[o*3+0]*x0 + w[o*3+1]*x1 + w[o*3+2]*x2 + bias[o];
        f0[(b*8+o)*N0 + n] = v;
    }
}

// megaA: blocks [0,32) -> fps1; [32,288) -> knn1 (2048q x 2048k)
__global__ __launch_bounds__(256) void k_megaA(const float* __restrict__ x,
                                               int* __restrict__ fps1,
                                               int* __restrict__ idx1) {
    __shared__ __align__(16) char sraw[33792];
    int bid = blockIdx.x;
    if (bid < 32) {
        dev_fps<N0, N1>(x, fps1, bid, sraw);
    } else {
        int r = bid - 32;
        dev_knn(N0, x, x, N0, idx1, r & 7, r >> 3, sraw);
    }
}

// megaB: [0,32) fps2; [32,96) knn2 (512q x 2048k); [96,160) knn3 (512q x 512k)
__global__ __launch_bounds__(256) void k_megaB(const float* __restrict__ cq1,
                                               const float* __restrict__ x,
                                               int* __restrict__ fps2,
                                               int* __restrict__ idx2,
                                               int* __restrict__ idx3) {
    __shared__ __align__(16) char sraw[33792];
    int bid = blockIdx.x;
    if (bid < 32) {
        dev_fps<N1, N2>(cq1, fps2, bid, sraw);
    } else if (bid < 96) {
        int r = bid - 32;
        dev_knn(N0, cq1, x, N1, idx2, r & 1, r >> 1, sraw);
    } else {
        int r = bid - 96;
        dev_knn(N1, cq1, cq1, N1, idx3, r & 1, r >> 1, sraw);
    }
}

// megaC: stage-4 knn + both gemms in one launch. grid.x = 1 + 64 + 16, grid.y = B.
__global__ __launch_bounds__(256) void k_megaC(const float* __restrict__ out_coor,
                                               const float* __restrict__ cq1,
                                               const float* __restrict__ f3,
                                               const float* __restrict__ fq3,
                                               const float* __restrict__ w4,
                                               int* __restrict__ idx4,
                                               float* __restrict__ g4,
                                               float* __restrict__ h4) {
    __shared__ __align__(16) char sraw[64 * 128 * 4];   // 32KB (>= knn 8KB)
    int b = blockIdx.y, xg = blockIdx.x;
    if (xg == 0) {
        dev_knn(N1, out_coor, cq1, N2, idx4, 0, b, sraw);
    } else if (xg < 1 + 64) {
        dev_gemm<64, 128>(f3, w4, N1, g4, false, xg - 1, b, (float*)sraw);
    } else {
        dev_gemm<64, 128>(fq3, w4, N2, h4, true, xg - 65, b, (float*)sraw);
    }
}

// stage-2 gemm pair: [0,128) g2 on f1 (Nk=2048); [128,160) h2 on fq1 (Nk=512)
__global__ __launch_bounds__(256) void k_gemmP2(const float* __restrict__ f1,
                                                const float* __restrict__ fq1,
                                                const float* __restrict__ w2,
                                                float* __restrict__ g2,
                                                float* __restrict__ h2) {
    __shared__ float ws[32 * 64];
    int b = blockIdx.y, xg = blockIdx.x;
    if (xg < 128) dev_gemm<32, 64>(f1,  w2, N0, g2, false, xg,       b, ws);
    else          dev_gemm<32, 64>(fq1, w2, N1, h2, true,  xg - 128, b, ws);
}

// paired gather: coords (3 ch) + features (Cf ch)
__global__ void k_gather_pair(const float* __restrict__ srcc, const float* __restrict__ srcf,
                              const int* __restrict__ idx, int Cf, int Nin, int S,
                              float* __restrict__ dstc, float* __restrict__ dstf) {
    int b = blockIdx.y;
    int t = blockIdx.x * blockDim.x + threadIdx.x;
    if (t >= (3 + Cf) * S) return;
    int c = t / S, s = t % S;
    int id = idx[(size_t)b*S + s];
    if (c < 3) dstc[((size_t)b*3 + c)*S + s] = srcc[((size_t)b*3 + c)*Nin + id];
    else {
        int cf = c - 3;
        dstf[((size_t)b*Cf + cf)*S + s] = srcf[((size_t)b*Cf + cf)*Nin + id];
    }
}

// dual-output GEMM (same input feeds both g and h): one read of f.
template<int C, int Cout>
__global__ void k_gemm2(const float* __restrict__ f, const float* __restrict__ w,
                        int Nk, float* __restrict__ g, float* __restrict__ h) {
    constexpr int OC = Cout / 4;
    __shared__ float ws[2 * C * Cout];
    int b = blockIdx.y;
    for (int i = threadIdx.x; i < C * Cout; i += blockDim.x) {
        int c = i / Cout, o = i % Cout;
        float lo = w[o*2*C + c];
        float hi = w[o*2*C + C + c];
        ws[(2*c)*Cout + o]   = lo;
        ws[(2*c+1)*Cout + o] = hi - lo;
    }
    __syncthreads();
    int t = blockIdx.x * blockDim.x + threadIdx.x;
    int j = t / OC, oc = t % OC;
    if (j >= Nk) return;
    const float* fb = f + (size_t)b*C*Nk;
    float g0=0.f,g1=0.f,g2=0.f,g3=0.f, h0=0.f,h1=0.f,h2=0.f,h3=0.f;
#pragma unroll
    for (int c = 0; c < C; c++) {
        float fv = fb[(size_t)c*Nk + j];
        float4 wl = *(const float4*)&ws[(2*c)*Cout + oc*4];
        float4 wd = *(const float4*)&ws[(2*c+1)*Cout + oc*4];
        g0 += fv*wl.x; g1 += fv*wl.y; g2 += fv*wl.z; g3 += fv*wl.w;
        h0 += fv*wd.x; h1 += fv*wd.y; h2 += fv*wd.z; h3 += fv*wd.w;
    }
    size_t o4 = ((size_t)b*Nk + j)*Cout + oc*4;
    *(float4*)&g[o4] = make_float4(g0,g1,g2,g3);
    *(float4*)&h[o4] = make_float4(h0,h1,h2,h3);
}

// fused: y[o,n,k] = g[j(n,k),o] + h[n,o]; max_k/min_k per (n,o) + group sum/sumsq
template<int Cout>
__global__ void k_stats_max(const float* __restrict__ g, const float* __restrict__ h,
                            const int* __restrict__ idx, int Nq, int Nk,
                            float* __restrict__ mx, float* __restrict__ mn,
                            double* __restrict__ stats) {
    constexpr int OC = Cout / 4;
    __shared__ float ssum[4], ssq[4];
    int b = blockIdx.y;
    if (threadIdx.x < 4) { ssum[threadIdx.x] = 0.f; ssq[threadIdx.x] = 0.f; }
    __syncthreads();
    int t = blockIdx.x * blockDim.x + threadIdx.x;
    int n = t / OC, oc = t % OC;
    float s = 0.f, ss = 0.f;
    int grp = 0;
    if (n < Nq) {
        grp = (oc * 16) / Cout;
        const int* ib = idx + ((size_t)b*Nq + n) * KN;
        float4 hv = *(const float4*)&h[((size_t)b*Nq + n)*Cout + oc*4];
        float4 m4 = make_float4(-3.4e38f, -3.4e38f, -3.4e38f, -3.4e38f);
        float4 n4 = make_float4( 3.4e38f,  3.4e38f,  3.4e38f,  3.4e38f);
#pragma unroll
        for (int k = 0; k < KN; k++) {
            int j = ib[k];
            float4 gv = *(const float4*)&g[((size_t)b*Nk + j)*Cout + oc*4];
            float y0 = gv.x + hv.x, y1 = gv.y + hv.y, y2 = gv.z + hv.z, y3 = gv.w + hv.w;
            m4.x = fmaxf(m4.x, y0); m4.y = fmaxf(m4.y, y1);
            m4.z = fmaxf(m4.z, y2); m4.w = fmaxf(m4.w, y3);
            n4.x = fminf(n4.x, y0); n4.y = fminf(n4.y, y1);
            n4.z = fminf(n4.z, y2); n4.w = fminf(n4.w, y3);
            s  += (y0 + y1) + (y2 + y3);
            ss += (y0*y0 + y1*y1) + (y2*y2 + y3*y3);
        }
        *(float4*)&mx[((size_t)b*Nq + n)*Cout + oc*4] = m4;
        *(float4*)&mn[((size_t)b*Nq + n)*Cout + oc*4] = n4;
    }
    atomicAdd(&ssum[grp], s);
    atomicAdd(&ssq[grp], ss);
    __syncthreads();
    if (threadIdx.x < 4) {
        atomicAdd(&stats[((size_t)b*4 + threadIdx.x)*2 + 0], (double)ssum[threadIdx.x]);
        atomicAdd(&stats[((size_t)b*4 + threadIdx.x)*2 + 1], (double)ssq[threadIdx.x]);
    }
}

// finalize: f_out = lrelu((sel - mean)*rstd*gamma + beta); sel = max if gamma>=0 else min
template<int Cout>
__global__ void k_finalize(const float* __restrict__ mx, const float* __restrict__ mn,
                           const double* __restrict__ stats,
                           const float* __restrict__ gamma, const float* __restrict__ beta,
                           int Nq, float* __restrict__ fout) {
    int b = blockIdx.y;
    int t = blockIdx.x * blockDim.x + threadIdx.x;
    if (t >= Cout * Nq) return;
    int o = t / Nq, n = t % Nq;
    int grp = o / (Cout / 4);
    double cnt = (double)(Cout / 4) * (double)Nq * (double)KN;
    double su = stats[((size_t)b*4 + grp)*2 + 0];
    double sq = stats[((size_t)b*4 + grp)*2 + 1];
    double m  = su / cnt;
    double vr = sq / cnt - m * m;
    float mean = (float)m;
    float rstd = rsqrtf((float)vr + 1e-5f);
    float ga = gamma[o], be = beta[o];
    float sel = (ga >= 0.f) ? mx[((size_t)b*Nq + n)*Cout + o]
                            : mn[((size_t)b*Nq + n)*Cout + o];
    float v = (sel - mean) * rstd * ga + be;
    fout[((size_t)b*Cout + o)*Nq + n] = (v >= 0.f) ? v : 0.2f * v;
}

// ---------------- launch ----------------
extern "C" void kernel_launch(void* const* d_in, const int* in_sizes, int n_in,
                              void* d_out, int out_size) {
    const float* x    = (const float*)d_in[0];
    const float* w_in = (const float*)d_in[1];
    const float* b_in = (const float*)d_in[2];
    const float* w1 = (const float*)d_in[3];
    const float* g1p = (const float*)d_in[4];
    const float* b1p = (const float*)d_in[5];
    const float* w2 = (const float*)d_in[6];
    const float* g2p = (const float*)d_in[7];
    const float* b2p = (const float*)d_in[8];
    const float* w3 = (const float*)d_in[9];
    const float* g3p = (const float*)d_in[10];
    const float* b3p = (const float*)d_in[11];
    const float* w4 = (const float*)d_in[12];
    const float* g4p = (const float*)d_in[13];
    const float* b4p = (const float*)d_in[14];

    float*  fb;  cudaGetSymbolAddress((void**)&fb,  d_fbuf);
    int*    ib;  cudaGetSymbolAddress((void**)&ib,  d_ibuf);
    double* st;  cudaGetSymbolAddress((void**)&st,  d_statsbuf);
    float*  out = (float*)d_out;

    float* f0  = fb + OFF_F0;
    float* g1  = fb + OFF_G1;  float* h1 = fb + OFF_H1;
    float* m1  = fb + OFF_M1;  float* mn1 = fb + OFF_MN1; float* f1 = fb + OFF_F1;
    float* cq1 = fb + OFF_CQ1; float* fq1 = fb + OFF_FQ1;
    float* g2  = fb + OFF_G2;  float* h2 = fb + OFF_H2;
    float* m2  = fb + OFF_M2;  float* mn2 = fb + OFF_MN2; float* f2 = fb + OFF_F2;
    float* g3  = fb + OFF_G3;  float* h3 = fb + OFF_H3;
    float* m3  = fb + OFF_M3;  float* mn3 = fb + OFF_MN3; float* f3 = fb + OFF_F3;
    float* fq3 = fb + OFF_FQ3;
    float* g4  = fb + OFF_G4;  float* h4 = fb + OFF_H4;
    float* m4  = fb + OFF_M4;  float* mn4 = fb + OFF_MN4;

    int* idx1 = ib + IOFF_IDX1; int* fps1 = ib + IOFF_FPS1;
    int* idx2 = ib + IOFF_IDX2; int* idx3 = ib + IOFF_IDX3;
    int* fps2 = ib + IOFF_FPS2; int* idx4 = ib + IOFF_IDX4;

    double* st1 = st + 0 * B * 8;
    double* st2 = st + 1 * B * 8;
    double* st3 = st + 2 * B * 8;
    double* st4 = st + 3 * B * 8;

    float* out_coor = out;                 // (B,3,128)
    float* out_f    = out + B * 3 * N2;    // (B,128,128)

    // 1: input linear (+ stats zeroing)
    k_lin_in<<<CDIV(B*N0, 256), 256>>>(x, w_in, b_in, f0, st);

    // 2: fps1 ∥ knn1
    k_megaA<<<32 + 256, 256>>>(x, fps1, idx1);

    // stage 1
    k_gemm2<8, 32><<<dim3(CDIV(N0*8, 256), B), 256>>>(f0, w1, N0, g1, h1);
    k_stats_max<32><<<dim3(CDIV(N0*8, 128), B), 128>>>(g1, h1, idx1, N0, N0, m1, mn1, st1);
    k_finalize<32><<<dim3(CDIV(32*N0, 256), B), 256>>>(m1, mn1, st1, g1p, b1p, N0, f1);

    // sample 512 (coords + features in one kernel)
    k_gather_pair<<<dim3(CDIV(35*N1, 256), B), 256>>>(x, f1, fps1, 32, N0, N1, cq1, fq1);

    // fps2 ∥ knn2 ∥ knn3
    k_megaB<<<32 + 64 + 64, 256>>>(cq1, x, fps2, idx2, idx3);

    // stage 2
    k_gemmP2<<<dim3(128 + 32, B), 256>>>(f1, fq1, w2, g2, h2);
    k_stats_max<64><<<dim3(CDIV(N1*16, 128), B), 128>>>(g2, h2, idx2, N1, N0, m2, mn2, st2);
    k_finalize<64><<<dim3(CDIV(64*N1, 256), B), 256>>>(m2, mn2, st2, g2p, b2p, N1, f2);

    // stage 3
    k_gemm2<64, 64><<<dim3(CDIV(N1*16, 256), B), 256>>>(f2, w3, N1, g3, h3);
    k_stats_max<64><<<dim3(CDIV(N1*16, 128), B), 128>>>(g3, h3, idx3, N1, N1, m3, mn3, st3);
    k_finalize<64><<<dim3(CDIV(64*N1, 256), B), 256>>>(m3, mn3, st3, g3p, b3p, N1, f3);

    // sample 128
    k_gather_pair<<<dim3(CDIV(67*N2, 256), B), 256>>>(cq1, f3, fps2, 64, N1, N2, out_coor, fq3);

    // stage 4: knn4 ∥ g4 ∥ h4
    k_megaC<<<dim3(1 + 64 + 16, B), 256>>>(out_coor, cq1, f3, fq3, w4, idx4, g4, h4);
    k_stats_max<128><<<dim3(CDIV(N2*32, 128), B), 128>>>(g4, h4, idx4, N2, N1, m4, mn4, st4);
    k_finalize<128><<<dim3(CDIV(128*N2, 256), B), 256>>>(m4, mn4, st4, g4p, b4p, N2, out_f);
}

// round 6
// speedup vs baseline: 1.5882x; 1.0271x over previous
#include <cuda_runtime.h>
#include <math.h>

#define CDIV(a,b) (((a)+(b)-1)/(b))

static constexpr int B  = 32;
static constexpr int KN = 16;
static constexpr int N0 = 2048, N1 = 512, N2 = 128;

// ---------------- scratch ----------------
static constexpr size_t OFF_G1  = 0;                                  // B*N0*32
static constexpr size_t OFF_H1  = OFF_G1  + (size_t)B*N0*32;
static constexpr size_t OFF_M1  = OFF_H1  + (size_t)B*N0*32;
static constexpr size_t OFF_MN1 = OFF_M1  + (size_t)B*N0*32;
static constexpr size_t OFF_F1  = OFF_MN1 + (size_t)B*N0*32;          // B*32*N0
static constexpr size_t OFF_CQ1 = OFF_F1  + (size_t)B*32*N0;          // B*3*N1
static constexpr size_t OFF_FQ1 = OFF_CQ1 + (size_t)B*3*N1;           // B*32*N1
static constexpr size_t OFF_G2  = OFF_FQ1 + (size_t)B*32*N1;          // B*N0*64
static constexpr size_t OFF_H2  = OFF_G2  + (size_t)B*N0*64;          // B*N1*64
static constexpr size_t OFF_M2  = OFF_H2  + (size_t)B*N1*64;
static constexpr size_t OFF_MN2 = OFF_M2  + (size_t)B*N1*64;
static constexpr size_t OFF_F2  = OFF_MN2 + (size_t)B*N1*64;          // B*64*N1
static constexpr size_t OFF_G3  = OFF_F2  + (size_t)B*64*N1;
static constexpr size_t OFF_H3  = OFF_G3  + (size_t)B*N1*64;
static constexpr size_t OFF_M3  = OFF_H3  + (size_t)B*N1*64;
static constexpr size_t OFF_MN3 = OFF_M3  + (size_t)B*N1*64;
static constexpr size_t OFF_F3  = OFF_MN3 + (size_t)B*N1*64;          // B*64*N1
static constexpr size_t OFF_FQ3 = OFF_F3  + (size_t)B*64*N1;          // B*64*N2
static constexpr size_t OFF_G4  = OFF_FQ3 + (size_t)B*64*N2;          // B*N1*128
static constexpr size_t OFF_H4  = OFF_G4  + (size_t)B*N1*128;         // B*N2*128
static constexpr size_t OFF_M4  = OFF_H4  + (size_t)B*N2*128;
static constexpr size_t OFF_MN4 = OFF_M4  + (size_t)B*N2*128;
static constexpr size_t FBUF_TOTAL = OFF_MN4 + (size_t)B*N2*128;

__device__ float d_fbuf[FBUF_TOTAL];

static constexpr size_t IOFF_IDX1 = 0;
static constexpr size_t IOFF_FPS1 = IOFF_IDX1 + (size_t)B*N0*KN;
static constexpr size_t IOFF_IDX2 = IOFF_FPS1 + (size_t)B*N1;
static constexpr size_t IOFF_IDX3 = IOFF_IDX2 + (size_t)B*N1*KN;
static constexpr size_t IOFF_FPS2 = IOFF_IDX3 + (size_t)B*N1*KN;
static constexpr size_t IOFF_IDX4 = IOFF_FPS2 + (size_t)B*N2;
static constexpr size_t IBUF_TOTAL = IOFF_IDX4 + (size_t)B*N2*KN;

__device__ int d_ibuf[IBUF_TOTAL];
__device__ double d_statsbuf[4 * B * 4 * 2];   // [layer][b][group][{sum,sumsq}]

// ---------------- device helpers ----------------

// KNN, R2-proven insertion chain; keys pre-transformed to (-2x,-2y,-2z,|k|^2)
// so d = |k|^2 - 2<q,k>  (drops per-query |q|^2: order & tie preserving).
// Strict '<' keeps lowest index on ties (matches jax.lax.top_k).
__device__ __forceinline__ void dev_knn(int NK, const float* __restrict__ cq,
                                        const float* __restrict__ ck,
                                        int Nq, int* __restrict__ idx_out,
                                        int bq, int b, char* sraw) {
    float4* skey = (float4*)sraw;
    const float* ckb = ck + (size_t)b*3*NK;
    for (int j = threadIdx.x; j < NK; j += 256) {
        float kx = ckb[j], ky = ckb[NK + j], kz = ckb[2*NK + j];
        skey[j] = make_float4(-2.f*kx, -2.f*ky, -2.f*kz, kx*kx + ky*ky + kz*kz);
    }
    __syncthreads();
    int q = bq * 256 + threadIdx.x;
    if (q >= Nq) return;
    const float* cqb = cq + (size_t)b*3*Nq;
    float qx = cqb[q], qy = cqb[Nq + q], qz = cqb[2*Nq + q];

    float bd[KN]; int bi[KN];
#pragma unroll
    for (int i = 0; i < KN; i++) { bd[i] = 3.4e38f; bi[i] = 0; }

    for (int j = 0; j < NK; j++) {
        float4 kk = skey[j];
        float d = fmaf(kk.x, qx, fmaf(kk.y, qy, fmaf(kk.z, qz, kk.w)));
        if (d < bd[KN-1]) {
            bd[KN-1] = d; bi[KN-1] = j;
#pragma unroll
            for (int i = KN-1; i > 0; --i) {
                if (bd[i] < bd[i-1]) {
                    float tv = bd[i]; bd[i] = bd[i-1]; bd[i-1] = tv;
                    int   ti = bi[i]; bi[i] = bi[i-1]; bi[i-1] = ti;
                }
            }
        }
    }
    int* ob = idx_out + ((size_t)b*Nq + q) * KN;
#pragma unroll
    for (int i = 0; i < KN; i++) ob[i] = bi[i];
}

// FPS, 256 threads, one barrier/iter, packed-u64 block merge.
template<int N, int S>
__device__ __forceinline__ void dev_fps(const float* __restrict__ coor,
                                        int* __restrict__ out, int b, char* sraw) {
    constexpr int BLK = 256, PPT = N / BLK, NW = BLK / 32;
    float* sx = (float*)sraw;
    float* sy = sx + N;
    float* sz = sy + N;
    unsigned long long* spk = (unsigned long long*)(sz + N);  // [2][NW]
    int t = threadIdx.x, lane = t & 31, w = t >> 5;
    const float* cb = coor + (size_t)b*3*N;

    float px[PPT], py[PPT], pz[PPT], dist[PPT];
#pragma unroll
    for (int p = 0; p < PPT; p++) {
        int i = t + p * BLK;
        float vx = cb[i], vy = cb[N + i], vz = cb[2*N + i];
        px[p] = vx; py[p] = vy; pz[p] = vz;
        sx[i] = vx; sy[i] = vy; sz[i] = vz;
        dist[p] = 1e10f;
    }
    __syncthreads();

    int last = 0;
    for (int s = 0; s < S; s++) {
        if (t == 0) out[(size_t)b*S + s] = last;
        float cx = sx[last], cy = sy[last], cz = sz[last];
        float bv = -1.0f; int bidx = 0;
#pragma unroll
        for (int p = 0; p < PPT; p++) {
            float dx = px[p]-cx, dy = py[p]-cy, dz = pz[p]-cz;
            float d = dx*dx + dy*dy + dz*dz;
            float nd = fminf(dist[p], d);
            dist[p] = nd;
            if (nd > bv) { bv = nd; bidx = t + p * BLK; }   // ascending idx => first-max
        }
        unsigned bits = __float_as_uint(fmaxf(bv, 0.0f));
        unsigned m  = __reduce_max_sync(0xffffffffu, bits);
        unsigned ci = (bits == m) ? (unsigned)bidx : 0xffffffffu;
        unsigned mi = __reduce_min_sync(0xffffffffu, ci);
        int buf = (s & 1) * NW;
        if (lane == 0)
            spk[buf + w] = ((unsigned long long)m << 32) | (unsigned)(~mi);
        __syncthreads();
        unsigned long long best = spk[buf + 0];
#pragma unroll
        for (int i2 = 1; i2 < NW; i2++) {
            unsigned long long v = spk[buf + i2];
            best = (v > best) ? v : best;     // max dist, tie -> max(~idx) = min idx
        }
        last = (int)(~(unsigned)best);
    }
}

// GEMM body, 256 threads: out[b,j,o] = sum_c wsel[o,c]*f[b,c,j]
template<int C, int Cout>
__device__ __forceinline__ void dev_gemm(const float* __restrict__ f,
                                         const float* __restrict__ w,
                                         int Nk, float* __restrict__ out,
                                         bool diff, int bq, int b, float* ws) {
    constexpr int OC = Cout / 4;
    for (int i = threadIdx.x; i < C * Cout; i += 256) {
        int c = i / Cout, o = i % Cout;
        float lo = w[o*2*C + c];
        float hi = w[o*2*C + C + c];
        ws[c*Cout + o] = diff ? (hi - lo) : lo;
    }
    __syncthreads();
    int t = bq * 256 + threadIdx.x;
    int j = t / OC, oc = t % OC;
    if (j >= Nk) return;
    const float* fb = f + (size_t)b*C*Nk;
    float a0 = 0.f, a1 = 0.f, a2 = 0.f, a3 = 0.f;
#pragma unroll
    for (int c = 0; c < C; c++) {
        float fv = fb[(size_t)c*Nk + j];
        float4 wv = *(const float4*)&ws[c*Cout + oc*4];
        a0 += fv * wv.x; a1 += fv * wv.y; a2 += fv * wv.z; a3 += fv * wv.w;
    }
    *(float4*)&out[((size_t)b*Nk + j)*Cout + oc*4] = make_float4(a0, a1, a2, a3);
}

// fused input-linear + stage-1 dual GEMM. One block handles 32 points of one batch.
// threads: oc = t&7 (4 outs), jo = t>>3.
__device__ __forceinline__ void dev_gemmIn(const float* __restrict__ x,
                                           const float* __restrict__ w_in,
                                           const float* __restrict__ b_in,
                                           const float* __restrict__ w1,
                                           float* __restrict__ g1, float* __restrict__ h1,
                                           int r, float* ws) {
    // ws: wlo[8*32], wdf[8*32], win[24], bin[8]
    float* wlo = ws; float* wdf = ws + 256; float* win = ws + 512; float* bin = ws + 536;
    int t = threadIdx.x;
    if (t < 256) {
        int o = t & 31, c = t >> 5;
        float lo = w1[o*16 + c];
        float hi = w1[o*16 + 8 + c];
        wlo[c*32 + o] = lo;
        wdf[c*32 + o] = hi - lo;
    }
    if (t < 24) win[t] = w_in[t];
    if (t < 8)  bin[t] = b_in[t];
    __syncthreads();
    int b = r >> 6, jb = r & 63;
    int oc = t & 7, jo = t >> 3;
    int j = jb * 32 + jo;
    float x0 = x[((size_t)b*3+0)*N0 + j];
    float x1 = x[((size_t)b*3+1)*N0 + j];
    float x2 = x[((size_t)b*3+2)*N0 + j];
    float f0[8];
#pragma unroll
    for (int o = 0; o < 8; o++)
        f0[o] = win[o*3+0]*x0 + win[o*3+1]*x1 + win[o*3+2]*x2 + bin[o];
    float g0=0.f,g1v=0.f,g2v=0.f,g3v=0.f, h0=0.f,h1v=0.f,h2v=0.f,h3v=0.f;
#pragma unroll
    for (int c = 0; c < 8; c++) {
        float fv = f0[c];
        float4 wl = *(const float4*)&wlo[c*32 + oc*4];
        float4 wd = *(const float4*)&wdf[c*32 + oc*4];
        g0 += fv*wl.x; g1v += fv*wl.y; g2v += fv*wl.z; g3v += fv*wl.w;
        h0 += fv*wd.x; h1v += fv*wd.y; h2v += fv*wd.z; h3v += fv*wd.w;
    }
    size_t o4 = ((size_t)b*N0 + j)*32 + oc*4;
    *(float4*)&g1[o4] = make_float4(g0,g1v,g2v,g3v);
    *(float4*)&h1[o4] = make_float4(h0,h1v,h2v,h3v);
}

// finalize value for one (b,n,o): lrelu((sel-mean)*rstd*gamma+beta)
__device__ __forceinline__ float finval(const float* __restrict__ mx, const float* __restrict__ mn,
                                        const double* __restrict__ st,
                                        const float* __restrict__ gamma, const float* __restrict__ beta,
                                        int b, int n, int o, int Nq, int C) {
    int grp = o / (C / 4);
    double cnt = (double)(C / 4) * (double)Nq * (double)KN;
    double su = st[((size_t)b*4 + grp)*2 + 0];
    double sq = st[((size_t)b*4 + grp)*2 + 1];
    double m  = su / cnt;
    double vr = sq / cnt - m * m;
    float mean = (float)m;
    float rstd = rsqrtf((float)vr + 1e-5f);
    float ga = gamma[o], be = beta[o];
    float sel = (ga >= 0.f) ? mx[((size_t)b*Nq + n)*C + o]
                            : mn[((size_t)b*Nq + n)*C + o];
    float v = (sel - mean) * rstd * ga + be;
    return (v >= 0.f) ? v : 0.2f * v;
}

// ---------------- kernels ----------------

// megaA: [0,32) fps1; [32,288) knn1; [288,292) zero stats; [292,2340) gemmIn
__global__ __launch_bounds__(256) void k_megaA(const float* __restrict__ x,
                                               const float* __restrict__ w_in,
                                               const float* __restrict__ b_in,
                                               const float* __restrict__ w1,
                                               int* __restrict__ fps1,
                                               int* __restrict__ idx1,
                                               float* __restrict__ g1,
                                               float* __restrict__ h1,
                                               double* __restrict__ st) {
    __shared__ __align__(16) char sraw[33792];
    int bid = blockIdx.x;
    if (bid < 32) {
        dev_fps<N0, N1>(x, fps1, bid, sraw);
    } else if (bid < 288) {
        int r = bid - 32;
        dev_knn(N0, x, x, N0, idx1, r & 7, r >> 3, sraw);
    } else if (bid < 292) {
        st[(bid - 288) * 256 + threadIdx.x] = 0.0;
    } else {
        dev_gemmIn(x, w_in, b_in, w1, g1, h1, bid - 292, (float*)sraw);
    }
}

// megaB: [0,32) fps2; [32,96) knn2; [96,160) knn3; [160,4256) g2; [4256,5280) h2
__global__ __launch_bounds__(256) void k_megaB(const float* __restrict__ cq1,
                                               const float* __restrict__ x,
                                               const float* __restrict__ f1,
                                               const float* __restrict__ fq1,
                                               const float* __restrict__ w2,
                                               int* __restrict__ fps2,
                                               int* __restrict__ idx2,
                                               int* __restrict__ idx3,
                                               float* __restrict__ g2,
                                               float* __restrict__ h2) {
    __shared__ __align__(16) char sraw[33792];
    int bid = blockIdx.x;
    if (bid < 32) {
        dev_fps<N1, N2>(cq1, fps2, bid, sraw);
    } else if (bid < 96) {
        int r = bid - 32;
        dev_knn(N0, cq1, x, N1, idx2, r & 1, r >> 1, sraw);
    } else if (bid < 160) {
        int r = bid - 96;
        dev_knn(N1, cq1, cq1, N1, idx3, r & 1, r >> 1, sraw);
    } else if (bid < 160 + 4096) {
        int r = bid - 160;
        dev_gemm<32, 64>(f1, w2, N0, g2, false, r & 127, r >> 7, (float*)sraw);
    } else {
        int r = bid - 4256;
        dev_gemm<32, 64>(fq1, w2, N1, h2, true, r & 31, r >> 5, (float*)sraw);
    }
}

// megaC: stage-4 knn + both gemms. grid (1+64+16, B).
__global__ __launch_bounds__(256) void k_megaC(const float* __restrict__ out_coor,
                                               const float* __restrict__ cq1,
                                               const float* __restrict__ f3,
                                               const float* __restrict__ fq3,
                                               const float* __restrict__ w4,
                                               int* __restrict__ idx4,
                                               float* __restrict__ g4,
                                               float* __restrict__ h4) {
    __shared__ __align__(16) char sraw[64 * 128 * 4];
    int b = blockIdx.y, xg = blockIdx.x;
    if (xg == 0) {
        dev_knn(N1, out_coor, cq1, N2, idx4, 0, b, sraw);
    } else if (xg < 1 + 64) {
        dev_gemm<64, 128>(f3, w4, N1, g4, false, xg - 1, b, (float*)sraw);
    } else {
        dev_gemm<64, 128>(fq3, w4, N2, h4, true, xg - 65, b, (float*)sraw);
    }
}

// fused stats+max: y = g[j]+h[n]; per-(n,o) max/min over k; group sum/sumsq.
template<int Cout>
__global__ void k_stats_max(const float* __restrict__ g, const float* __restrict__ h,
                            const int* __restrict__ idx, int Nq, int Nk,
                            float* __restrict__ mx, float* __restrict__ mn,
                            double* __restrict__ stats) {
    constexpr int OC = Cout / 4;
    __shared__ float ssum[4], ssq[4];
    int b = blockIdx.y;
    if (threadIdx.x < 4) { ssum[threadIdx.x] = 0.f; ssq[threadIdx.x] = 0.f; }
    __syncthreads();
    int t = blockIdx.x * blockDim.x + threadIdx.x;
    int n = t / OC, oc = t % OC;
    float s = 0.f, ss = 0.f;
    int grp = 0;
    if (n < Nq) {
        grp = (oc * 16) / Cout;
        const int4* ib4 = (const int4*)(idx + ((size_t)b*Nq + n) * KN);
        int jj[KN];
#pragma unroll
        for (int u = 0; u < 4; u++) {
            int4 v = ib4[u];
            jj[u*4+0] = v.x; jj[u*4+1] = v.y; jj[u*4+2] = v.z; jj[u*4+3] = v.w;
        }
        float4 hv = *(const float4*)&h[((size_t)b*Nq + n)*Cout + oc*4];
        float4 m4 = make_float4(-3.4e38f, -3.4e38f, -3.4e38f, -3.4e38f);
        float4 n4 = make_float4( 3.4e38f,  3.4e38f,  3.4e38f,  3.4e38f);
#pragma unroll
        for (int k = 0; k < KN; k++) {
            float4 gv = *(const float4*)&g[((size_t)b*Nk + jj[k])*Cout + oc*4];
            float y0 = gv.x + hv.x, y1 = gv.y + hv.y, y2 = gv.z + hv.z, y3 = gv.w + hv.w;
            m4.x = fmaxf(m4.x, y0); m4.y = fmaxf(m4.y, y1);
            m4.z = fmaxf(m4.z, y2); m4.w = fmaxf(m4.w, y3);
            n4.x = fminf(n4.x, y0); n4.y = fminf(n4.y, y1);
            n4.z = fminf(n4.z, y2); n4.w = fminf(n4.w, y3);
            s  += (y0 + y1) + (y2 + y3);
            ss += (y0*y0 + y1*y1) + (y2*y2 + y3*y3);
        }
        *(float4*)&mx[((size_t)b*Nq + n)*Cout + oc*4] = m4;
        *(float4*)&mn[((size_t)b*Nq + n)*Cout + oc*4] = n4;
    }
    atomicAdd(&ssum[grp], s);
    atomicAdd(&ssq[grp], ss);
    __syncthreads();
    if (threadIdx.x < 4) {
        atomicAdd(&stats[((size_t)b*4 + threadIdx.x)*2 + 0], (double)ssum[threadIdx.x]);
        atomicAdd(&stats[((size_t)b*4 + threadIdx.x)*2 + 1], (double)ssq[threadIdx.x]);
    }
}

// finalize full feature map (f[b,o,n]); grid (FB, B)
template<int Cout>
__global__ void k_fin(const float* __restrict__ mx, const float* __restrict__ mn,
                      const double* __restrict__ stats,
                      const float* __restrict__ gamma, const float* __restrict__ beta,
                      int Nq, float* __restrict__ fout) {
    int b = blockIdx.y;
    int t = blockIdx.x * blockDim.x + threadIdx.x;
    if (t >= Cout * Nq) return;
    int o = t / Nq, n = t % Nq;
    fout[((size_t)b*Cout + o)*Nq + n] = finval(mx, mn, stats, gamma, beta, b, n, o, Nq, Cout);
}

// finalize full + gather sampled (coords + recomputed features). grid (FB + GB, B).
template<int Cout, int FB>
__global__ void k_finGather(const float* __restrict__ mx, const float* __restrict__ mn,
                            const double* __restrict__ stats,
                            const float* __restrict__ gamma, const float* __restrict__ beta,
                            int Nq, float* __restrict__ fout,
                            const float* __restrict__ srcc, const int* __restrict__ fpsi,
                            int S, float* __restrict__ dstc, float* __restrict__ dstf) {
    int b = blockIdx.y;
    if (blockIdx.x < FB) {
        int t = blockIdx.x * blockDim.x + threadIdx.x;
        if (t >= Cout * Nq) return;
        int o = t / Nq, n = t % Nq;
        fout[((size_t)b*Cout + o)*Nq + n] = finval(mx, mn, stats, gamma, beta, b, n, o, Nq, Cout);
    } else {
        int t = (blockIdx.x - FB) * blockDim.x + threadIdx.x;
        if (t >= (3 + Cout) * S) return;
        int c = t / S, s = t % S;
        int id = fpsi[(size_t)b*S + s];
        if (c < 3)
            dstc[((size_t)b*3 + c)*S + s] = srcc[((size_t)b*3 + c)*Nq + id];
        else
            dstf[((size_t)b*Cout + (c-3))*S + s] =
                finval(mx, mn, stats, gamma, beta, b, id, c-3, Nq, Cout);
    }
}

// stage-3 dual GEMM (g3,h3 from f2)
template<int C, int Cout>
__global__ void k_gemm2(const float* __restrict__ f, const float* __restrict__ w,
                        int Nk, float* __restrict__ g, float* __restrict__ h) {
    constexpr int OC = Cout / 4;
    __shared__ float ws[2 * C * Cout];
    int b = blockIdx.y;
    for (int i = threadIdx.x; i < C * Cout; i += blockDim.x) {
        int c = i / Cout, o = i % Cout;
        float lo = w[o*2*C + c];
        float hi = w[o*2*C + C + c];
        ws[(2*c)*Cout + o]   = lo;
        ws[(2*c+1)*Cout + o] = hi - lo;
    }
    __syncthreads();
    int t = blockIdx.x * blockDim.x + threadIdx.x;
    int j = t / OC, oc = t % OC;
    if (j >= Nk) return;
    const float* fb = f + (size_t)b*C*Nk;
    float g0=0.f,g1=0.f,g2=0.f,g3=0.f, h0=0.f,h1=0.f,h2=0.f,h3=0.f;
#pragma unroll
    for (int c = 0; c < C; c++) {
        float fv = fb[(size_t)c*Nk + j];
        float4 wl = *(const float4*)&ws[(2*c)*Cout + oc*4];
        float4 wd = *(const float4*)&ws[(2*c+1)*Cout + oc*4];
        g0 += fv*wl.x; g1 += fv*wl.y; g2 += fv*wl.z; g3 += fv*wl.w;
        h0 += fv*wd.x; h1 += fv*wd.y; h2 += fv*wd.z; h3 += fv*wd.w;
    }
    size_t o4 = ((size_t)b*Nk + j)*Cout + oc*4;
    *(float4*)&g[o4] = make_float4(g0,g1,g2,g3);
    *(float4*)&h[o4] = make_float4(h0,h1,h2,h3);
}

// ---------------- launch ----------------
extern "C" void kernel_launch(void* const* d_in, const int* in_sizes, int n_in,
                              void* d_out, int out_size) {
    const float* x    = (const float*)d_in[0];
    const float* w_in = (const float*)d_in[1];
    const float* b_in = (const float*)d_in[2];
    const float* w1 = (const float*)d_in[3];
    const float* g1p = (const float*)d_in[4];
    const float* b1p = (const float*)d_in[5];
    const float* w2 = (const float*)d_in[6];
    const float* g2p = (const float*)d_in[7];
    const float* b2p = (const float*)d_in[8];
    const float* w3 = (const float*)d_in[9];
    const float* g3p = (const float*)d_in[10];
    const float* b3p = (const float*)d_in[11];
    const float* w4 = (const float*)d_in[12];
    const float* g4p = (const float*)d_in[13];
    const float* b4p = (const float*)d_in[14];

    float*  fb;  cudaGetSymbolAddress((void**)&fb,  d_fbuf);
    int*    ib;  cudaGetSymbolAddress((void**)&ib,  d_ibuf);
    double* st;  cudaGetSymbolAddress((void**)&st,  d_statsbuf);
    float*  out = (float*)d_out;

    float* g1  = fb + OFF_G1;  float* h1 = fb + OFF_H1;
    float* m1  = fb + OFF_M1;  float* mn1 = fb + OFF_MN1; float* f1 = fb + OFF_F1;
    float* cq1 = fb + OFF_CQ1; float* fq1 = fb + OFF_FQ1;
    float* g2  = fb + OFF_G2;  float* h2 = fb + OFF_H2;
    float* m2  = fb + OFF_M2;  float* mn2 = fb + OFF_MN2; float* f2 = fb + OFF_F2;
    float* g3  = fb + OFF_G3;  float* h3 = fb + OFF_H3;
    float* m3  = fb + OFF_M3;  float* mn3 = fb + OFF_MN3; float* f3 = fb + OFF_F3;
    float* fq3 = fb + OFF_FQ3;
    float* g4  = fb + OFF_G4;  float* h4 = fb + OFF_H4;
    float* m4  = fb + OFF_M4;  float* mn4 = fb + OFF_MN4;

    int* idx1 = ib + IOFF_IDX1; int* fps1 = ib + IOFF_FPS1;
    int* idx2 = ib + IOFF_IDX2; int* idx3 = ib + IOFF_IDX3;
    int* fps2 = ib + IOFF_FPS2; int* idx4 = ib + IOFF_IDX4;

    double* st1 = st + 0 * B * 8;
    double* st2 = st + 1 * B * 8;
    double* st3 = st + 2 * B * 8;
    double* st4 = st + 3 * B * 8;

    float* out_coor = out;                 // (B,3,128)
    float* out_f    = out + B * 3 * N2;    // (B,128,128)

    // 1: fps1 ∥ knn1 ∥ (lin+gemm1 fused) ∥ stats zeroing
    k_megaA<<<292 + 2048, 256>>>(x, w_in, b_in, w1, fps1, idx1, g1, h1, st);

    // 2-3: stage-1 stats, then finalize-full + gather (cq1, fq1)
    k_stats_max<32><<<dim3(CDIV(N0*8, 128), B), 128>>>(g1, h1, idx1, N0, N0, m1, mn1, st1);
    k_finGather<32, 256><<<dim3(256 + CDIV(35*N1, 256), B), 256>>>(
        m1, mn1, st1, g1p, b1p, N0, f1, x, fps1, N1, cq1, fq1);

    // 4: fps2 ∥ knn2 ∥ knn3 ∥ g2 ∥ h2
    k_megaB<<<160 + 4096 + 1024, 256>>>(cq1, x, f1, fq1, w2, fps2, idx2, idx3, g2, h2);

    // 5-6: stage-2 stats + finalize
    k_stats_max<64><<<dim3(CDIV(N1*16, 128), B), 128>>>(g2, h2, idx2, N1, N0, m2, mn2, st2);
    k_fin<64><<<dim3(CDIV(64*N1, 256), B), 256>>>(m2, mn2, st2, g2p, b2p, N1, f2);

    // 7-9: stage 3
    k_gemm2<64, 64><<<dim3(CDIV(N1*16, 256), B), 256>>>(f2, w3, N1, g3, h3);
    k_stats_max<64><<<dim3(CDIV(N1*16, 128), B), 128>>>(g3, h3, idx3, N1, N1, m3, mn3, st3);
    k_finGather<64, 128><<<dim3(128 + CDIV(67*N2, 256), B), 256>>>(
        m3, mn3, st3, g3p, b3p, N1, f3, cq1, fps2, N2, out_coor, fq3);

    // 10-12: stage 4
    k_megaC<<<dim3(1 + 64 + 16, B), 256>>>(out_coor, cq1, f3, fq3, w4, idx4, g4, h4);
    k_stats_max<128><<<dim3(CDIV(N2*32, 128), B), 128>>>(g4, h4, idx4, N2, N1, m4, mn4, st4);
    k_fin<128><<<dim3(CDIV(128*N2, 256), B), 256>>>(m4, mn4, st4, g4p, b4p, N2, out_f);
}

// round 7
// speedup vs baseline: 2.4865x; 1.5656x over previous
#include <cuda_runtime.h>
#include <math.h>

#define CDIV(a,b) (((a)+(b)-1)/(b))

static constexpr int B  = 32;
static constexpr int KN = 16;
static constexpr int N0 = 2048, N1 = 512, N2 = 128;

// ---------------- scratch ----------------
static constexpr size_t OFF_G1  = 0;                                  // B*N0*32
static constexpr size_t OFF_H1  = OFF_G1  + (size_t)B*N0*32;
static constexpr size_t OFF_M1  = OFF_H1  + (size_t)B*N0*32;
static constexpr size_t OFF_MN1 = OFF_M1  + (size_t)B*N0*32;
static constexpr size_t OFF_F1  = OFF_MN1 + (size_t)B*N0*32;          // B*32*N0
static constexpr size_t OFF_CQ1 = OFF_F1  + (size_t)B*32*N0;          // B*3*N1
static constexpr size_t OFF_FQ1 = OFF_CQ1 + (size_t)B*3*N1;           // B*32*N1
static constexpr size_t OFF_G2  = OFF_FQ1 + (size_t)B*32*N1;          // B*N0*64
static constexpr size_t OFF_H2  = OFF_G2  + (size_t)B*N0*64;          // B*N1*64
static constexpr size_t OFF_M2  = OFF_H2  + (size_t)B*N1*64;
static constexpr size_t OFF_MN2 = OFF_M2  + (size_t)B*N1*64;
static constexpr size_t OFF_F2  = OFF_MN2 + (size_t)B*N1*64;          // B*64*N1
static constexpr size_t OFF_G3  = OFF_F2  + (size_t)B*64*N1;
static constexpr size_t OFF_H3  = OFF_G3  + (size_t)B*N1*64;
static constexpr size_t OFF_M3  = OFF_H3  + (size_t)B*N1*64;
static constexpr size_t OFF_MN3 = OFF_M3  + (size_t)B*N1*64;
static constexpr size_t OFF_F3  = OFF_MN3 + (size_t)B*N1*64;          // B*64*N1
static constexpr size_t OFF_FQ3 = OFF_F3  + (size_t)B*64*N1;          // B*64*N2
static constexpr size_t OFF_G4  = OFF_FQ3 + (size_t)B*64*N2;          // B*N1*128
static constexpr size_t OFF_H4  = OFF_G4  + (size_t)B*N1*128;         // B*N2*128
static constexpr size_t OFF_M4  = OFF_H4  + (size_t)B*N2*128;
static constexpr size_t OFF_MN4 = OFF_M4  + (size_t)B*N2*128;
static constexpr size_t FBUF_TOTAL = OFF_MN4 + (size_t)B*N2*128;

__device__ float d_fbuf[FBUF_TOTAL];

static constexpr size_t IOFF_IDX1 = 0;
static constexpr size_t IOFF_FPS1 = IOFF_IDX1 + (size_t)B*N0*KN;
static constexpr size_t IOFF_IDX2 = IOFF_FPS1 + (size_t)B*N1;
static constexpr size_t IOFF_IDX3 = IOFF_IDX2 + (size_t)B*N1*KN;
static constexpr size_t IOFF_FPS2 = IOFF_IDX3 + (size_t)B*N1*KN;
static constexpr size_t IOFF_IDX4 = IOFF_FPS2 + (size_t)B*N2;
static constexpr size_t IBUF_TOTAL = IOFF_IDX4 + (size_t)B*N2*KN;

__device__ int d_ibuf[IBUF_TOTAL];
__device__ double d_statsbuf[4 * B * 4 * 2];   // [layer][b][group][{sum,sumsq}]

// ---------------- device helpers ----------------

// Warp-cooperative KNN: ONE QUERY PER WARP; 8 queries per 256-thread block.
// Lane l<16 holds the l-th smallest (dist,idx) so far, sorted ascending.
// Keys pre-transformed to (-2x,-2y,-2z,|k|^2): d = |k|^2 - 2<q,k>
// (constant |q|^2 dropped: order & ties preserved).
// Acceptance strict '<'; position counts (bd <= d) so earlier-j stays ahead
// on ties and the evicted boundary element is the latest-j one: exactly
// jax.lax.top_k set semantics.
__device__ __forceinline__ void dev_knn(int NK, const float* __restrict__ cq,
                                        const float* __restrict__ ck,
                                        int Nq, int* __restrict__ idx_out,
                                        int qblk, int b, char* sraw) {
    float4* skey = (float4*)sraw;
    const float* ckb = ck + (size_t)b*3*NK;
    for (int j = threadIdx.x; j < NK; j += 256) {
        float kx = ckb[j], ky = ckb[NK + j], kz = ckb[2*NK + j];
        skey[j] = make_float4(-2.f*kx, -2.f*ky, -2.f*kz, kx*kx + ky*ky + kz*kz);
    }
    __syncthreads();
    int w = threadIdx.x >> 5, lane = threadIdx.x & 31;
    int q = qblk * 8 + w;
    const float* cqb = cq + (size_t)b*3*Nq;
    float qx = cqb[q], qy = cqb[Nq + q], qz = cqb[2*Nq + q];

    float bd = 3.4e38f;
    int   bj = 0;

    for (int j0 = 0; j0 < NK; j0 += 32) {
        float4 kk = skey[j0 + lane];
        float d = fmaf(kk.x, qx, fmaf(kk.y, qy, fmaf(kk.z, qz, kk.w)));
        float th = __shfl_sync(0xffffffffu, bd, 15);
        unsigned hits = __ballot_sync(0xffffffffu, d < th);
        while (hits) {
            int s = __ffs(hits) - 1;          // lowest lane first => ascending j
            hits &= hits - 1;
            float dd = __shfl_sync(0xffffffffu, d, s);
            th = __shfl_sync(0xffffffffu, bd, 15);    // refreshed threshold
            if (dd < th) {                    // dd,th warp-uniform: no divergence
                int r = __popc(__ballot_sync(0xffffffffu, bd <= dd) & 0xFFFFu);
                float pd = __shfl_up_sync(0xffffffffu, bd, 1);
                int   pj = __shfl_up_sync(0xffffffffu, bj, 1);
                if (lane > r && lane < 16) { bd = pd; bj = pj; }
                if (lane == r)             { bd = dd; bj = j0 + s; }
            }
        }
    }
    if (lane < 16) idx_out[((size_t)b*Nq + q)*KN + lane] = bj;
}

// FPS, 256 threads, one barrier/iter, packed-u64 block merge (proven R6).
template<int N, int S>
__device__ __forceinline__ void dev_fps(const float* __restrict__ coor,
                                        int* __restrict__ out, int b, char* sraw) {
    constexpr int BLK = 256, PPT = N / BLK, NW = BLK / 32;
    float* sx = (float*)sraw;
    float* sy = sx + N;
    float* sz = sy + N;
    unsigned long long* spk = (unsigned long long*)(sz + N);  // [2][NW]
    int t = threadIdx.x, lane = t & 31, w = t >> 5;
    const float* cb = coor + (size_t)b*3*N;

    float px[PPT], py[PPT], pz[PPT], dist[PPT];
#pragma unroll
    for (int p = 0; p < PPT; p++) {
        int i = t + p * BLK;
        float vx = cb[i], vy = cb[N + i], vz = cb[2*N + i];
        px[p] = vx; py[p] = vy; pz[p] = vz;
        sx[i] = vx; sy[i] = vy; sz[i] = vz;
        dist[p] = 1e10f;
    }
    __syncthreads();

    int last = 0;
    for (int s = 0; s < S; s++) {
        if (t == 0) out[(size_t)b*S + s] = last;
        float cx = sx[last], cy = sy[last], cz = sz[last];
        float bv = -1.0f; int bidx = 0;
#pragma unroll
        for (int p = 0; p < PPT; p++) {
            float dx = px[p]-cx, dy = py[p]-cy, dz = pz[p]-cz;
            float d = dx*dx + dy*dy + dz*dz;
            float nd = fminf(dist[p], d);
            dist[p] = nd;
            if (nd > bv) { bv = nd; bidx = t + p * BLK; }
        }
        unsigned bits = __float_as_uint(fmaxf(bv, 0.0f));
        unsigned m  = __reduce_max_sync(0xffffffffu, bits);
        unsigned ci = (bits == m) ? (unsigned)bidx : 0xffffffffu;
        unsigned mi = __reduce_min_sync(0xffffffffu, ci);
        int buf = (s & 1) * NW;
        if (lane == 0)
            spk[buf + w] = ((unsigned long long)m << 32) | (unsigned)(~mi);
        __syncthreads();
        unsigned long long best = spk[buf + 0];
#pragma unroll
        for (int i2 = 1; i2 < NW; i2++) {
            unsigned long long v = spk[buf + i2];
            best = (v > best) ? v : best;
        }
        last = (int)(~(unsigned)best);
    }
}

// GEMM body, 256 threads: out[b,j,o] = sum_c wsel[o,c]*f[b,c,j]
template<int C, int Cout>
__device__ __forceinline__ void dev_gemm(const float* __restrict__ f,
                                         const float* __restrict__ w,
                                         int Nk, float* __restrict__ out,
                                         bool diff, int bq, int b, float* ws) {
    constexpr int OC = Cout / 4;
    for (int i = threadIdx.x; i < C * Cout; i += 256) {
        int c = i / Cout, o = i % Cout;
        float lo = w[o*2*C + c];
        float hi = w[o*2*C + C + c];
        ws[c*Cout + o] = diff ? (hi - lo) : lo;
    }
    __syncthreads();
    int t = bq * 256 + threadIdx.x;
    int j = t / OC, oc = t % OC;
    if (j >= Nk) return;
    const float* fb = f + (size_t)b*C*Nk;
    float a0 = 0.f, a1 = 0.f, a2 = 0.f, a3 = 0.f;
#pragma unroll
    for (int c = 0; c < C; c++) {
        float fv = fb[(size_t)c*Nk + j];
        float4 wv = *(const float4*)&ws[c*Cout + oc*4];
        a0 += fv * wv.x; a1 += fv * wv.y; a2 += fv * wv.z; a3 += fv * wv.w;
    }
    *(float4*)&out[((size_t)b*Nk + j)*Cout + oc*4] = make_float4(a0, a1, a2, a3);
}

// fused input-linear + stage-1 dual GEMM (proven R6).
__device__ __forceinline__ void dev_gemmIn(const float* __restrict__ x,
                                           const float* __restrict__ w_in,
                                           const float* __restrict__ b_in,
                                           const float* __restrict__ w1,
                                           float* __restrict__ g1, float* __restrict__ h1,
                                           int r, float* ws) {
    float* wlo = ws; float* wdf = ws + 256; float* win = ws + 512; float* bin = ws + 536;
    int t = threadIdx.x;
    if (t < 256) {
        int o = t & 31, c = t >> 5;
        float lo = w1[o*16 + c];
        float hi = w1[o*16 + 8 + c];
        wlo[c*32 + o] = lo;
        wdf[c*32 + o] = hi - lo;
    }
    if (t < 24) win[t] = w_in[t];
    if (t < 8)  bin[t] = b_in[t];
    __syncthreads();
    int b = r >> 6, jb = r & 63;
    int oc = t & 7, jo = t >> 3;
    int j = jb * 32 + jo;
    float x0 = x[((size_t)b*3+0)*N0 + j];
    float x1 = x[((size_t)b*3+1)*N0 + j];
    float x2 = x[((size_t)b*3+2)*N0 + j];
    float f0[8];
#pragma unroll
    for (int o = 0; o < 8; o++)
        f0[o] = win[o*3+0]*x0 + win[o*3+1]*x1 + win[o*3+2]*x2 + bin[o];
    float g0=0.f,g1v=0.f,g2v=0.f,g3v=0.f, h0=0.f,h1v=0.f,h2v=0.f,h3v=0.f;
#pragma unroll
    for (int c = 0; c < 8; c++) {
        float fv = f0[c];
        float4 wl = *(const float4*)&wlo[c*32 + oc*4];
        float4 wd = *(const float4*)&wdf[c*32 + oc*4];
        g0 += fv*wl.x; g1v += fv*wl.y; g2v += fv*wl.z; g3v += fv*wl.w;
        h0 += fv*wd.x; h1v += fv*wd.y; h2v += fv*wd.z; h3v += fv*wd.w;
    }
    size_t o4 = ((size_t)b*N0 + j)*32 + oc*4;
    *(float4*)&g1[o4] = make_float4(g0,g1v,g2v,g3v);
    *(float4*)&h1[o4] = make_float4(h0,h1v,h2v,h3v);
}

// finalize value for one (b,n,o)
__device__ __forceinline__ float finval(const float* __restrict__ mx, const float* __restrict__ mn,
                                        const double* __restrict__ st,
                                        const float* __restrict__ gamma, const float* __restrict__ beta,
                                        int b, int n, int o, int Nq, int C) {
    int grp = o / (C / 4);
    double cnt = (double)(C / 4) * (double)Nq * (double)KN;
    double su = st[((size_t)b*4 + grp)*2 + 0];
    double sq = st[((size_t)b*4 + grp)*2 + 1];
    double m  = su / cnt;
    double vr = sq / cnt - m * m;
    float mean = (float)m;
    float rstd = rsqrtf((float)vr + 1e-5f);
    float ga = gamma[o], be = beta[o];
    float sel = (ga >= 0.f) ? mx[((size_t)b*Nq + n)*C + o]
                            : mn[((size_t)b*Nq + n)*C + o];
    float v = (sel - mean) * rstd * ga + be;
    return (v >= 0.f) ? v : 0.2f * v;
}

// ---------------- kernels ----------------

// megaA: [0,32) fps1; [32,8224) knn1 (warp/query); [8224,8228) zero; [8228,10276) gemmIn
__global__ __launch_bounds__(256) void k_megaA(const float* __restrict__ x,
                                               const float* __restrict__ w_in,
                                               const float* __restrict__ b_in,
                                               const float* __restrict__ w1,
                                               int* __restrict__ fps1,
                                               int* __restrict__ idx1,
                                               float* __restrict__ g1,
                                               float* __restrict__ h1,
                                               double* __restrict__ st) {
    __shared__ __align__(16) char sraw[33792];
    int bid = blockIdx.x;
    if (bid < 32) {
        dev_fps<N0, N1>(x, fps1, bid, sraw);
    } else if (bid < 32 + 8192) {
        int r = bid - 32;                     // b = r>>8, qblk = r&255
        dev_knn(N0, x, x, N0, idx1, r & 255, r >> 8, sraw);
    } else if (bid < 32 + 8192 + 4) {
        st[(bid - 8224) * 256 + threadIdx.x] = 0.0;
    } else {
        dev_gemmIn(x, w_in, b_in, w1, g1, h1, bid - 8228, (float*)sraw);
    }
}

// megaB: [0,32) fps2; [32,2080) knn2; [2080,4128) knn3; [4128,8224) g2; [8224,9248) h2
__global__ __launch_bounds__(256) void k_megaB(const float* __restrict__ cq1,
                                               const float* __restrict__ x,
                                               const float* __restrict__ f1,
                                               const float* __restrict__ fq1,
                                               const float* __restrict__ w2,
                                               int* __restrict__ fps2,
                                               int* __restrict__ idx2,
                                               int* __restrict__ idx3,
                                               float* __restrict__ g2,
                                               float* __restrict__ h2) {
    __shared__ __align__(16) char sraw[33792];
    int bid = blockIdx.x;
    if (bid < 32) {
        dev_fps<N1, N2>(cq1, fps2, bid, sraw);
    } else if (bid < 2080) {
        int r = bid - 32;                     // 64 qblks per batch
        dev_knn(N0, cq1, x, N1, idx2, r & 63, r >> 6, sraw);
    } else if (bid < 4128) {
        int r = bid - 2080;
        dev_knn(N1, cq1, cq1, N1, idx3, r & 63, r >> 6, sraw);
    } else if (bid < 8224) {
        int r = bid - 4128;
        dev_gemm<32, 64>(f1, w2, N0, g2, false, r & 127, r >> 7, (float*)sraw);
    } else {
        int r = bid - 8224;
        dev_gemm<32, 64>(fq1, w2, N1, h2, true, r & 31, r >> 5, (float*)sraw);
    }
}

// megaC: [0,512) knn4 (warp/query); [512,2560) g4; [2560,3072) h4
__global__ __launch_bounds__(256) void k_megaC(const float* __restrict__ out_coor,
                                               const float* __restrict__ cq1,
                                               const float* __restrict__ f3,
                                               const float* __restrict__ fq3,
                                               const float* __restrict__ w4,
                                               int* __restrict__ idx4,
                                               float* __restrict__ g4,
                                               float* __restrict__ h4) {
    __shared__ __align__(16) char sraw[33792];
    int bid = blockIdx.x;
    if (bid < 512) {
        int r = bid;                          // 16 qblks per batch
        dev_knn(N1, out_coor, cq1, N2, idx4, r & 15, r >> 4, sraw);
    } else if (bid < 512 + 2048) {
        int r = bid - 512;
        dev_gemm<64, 128>(f3, w4, N1, g4, false, r & 63, r >> 6, (float*)sraw);
    } else {
        int r = bid - 2560;
        dev_gemm<64, 128>(fq3, w4, N2, h4, true, r & 15, r >> 4, (float*)sraw);
    }
}

// fused stats+max
template<int Cout>
__global__ void k_stats_max(const float* __restrict__ g, const float* __restrict__ h,
                            const int* __restrict__ idx, int Nq, int Nk,
                            float* __restrict__ mx, float* __restrict__ mn,
                            double* __restrict__ stats) {
    constexpr int OC = Cout / 4;
    __shared__ float ssum[4], ssq[4];
    int b = blockIdx.y;
    if (threadIdx.x < 4) { ssum[threadIdx.x] = 0.f; ssq[threadIdx.x] = 0.f; }
    __syncthreads();
    int t = blockIdx.x * blockDim.x + threadIdx.x;
    int n = t / OC, oc = t % OC;
    float s = 0.f, ss = 0.f;
    int grp = 0;
    if (n < Nq) {
        grp = (oc * 16) / Cout;
        const int4* ib4 = (const int4*)(idx + ((size_t)b*Nq + n) * KN);
        int jj[KN];
#pragma unroll
        for (int u = 0; u < 4; u++) {
            int4 v = ib4[u];
            jj[u*4+0] = v.x; jj[u*4+1] = v.y; jj[u*4+2] = v.z; jj[u*4+3] = v.w;
        }
        float4 hv = *(const float4*)&h[((size_t)b*Nq + n)*Cout + oc*4];
        float4 m4 = make_float4(-3.4e38f, -3.4e38f, -3.4e38f, -3.4e38f);
        float4 n4 = make_float4( 3.4e38f,  3.4e38f,  3.4e38f,  3.4e38f);
#pragma unroll
        for (int k = 0; k < KN; k++) {
            float4 gv = *(const float4*)&g[((size_t)b*Nk + jj[k])*Cout + oc*4];
            float y0 = gv.x + hv.x, y1 = gv.y + hv.y, y2 = gv.z + hv.z, y3 = gv.w + hv.w;
            m4.x = fmaxf(m4.x, y0); m4.y = fmaxf(m4.y, y1);
            m4.z = fmaxf(m4.z, y2); m4.w = fmaxf(m4.w, y3);
            n4.x = fminf(n4.x, y0); n4.y = fminf(n4.y, y1);
            n4.z = fminf(n4.z, y2); n4.w = fminf(n4.w, y3);
            s  += (y0 + y1) + (y2 + y3);
            ss += (y0*y0 + y1*y1) + (y2*y2 + y3*y3);
        }
        *(float4*)&mx[((size_t)b*Nq + n)*Cout + oc*4] = m4;
        *(float4*)&mn[((size_t)b*Nq + n)*Cout + oc*4] = n4;
    }
    atomicAdd(&ssum[grp], s);
    atomicAdd(&ssq[grp], ss);
    __syncthreads();
    if (threadIdx.x < 4) {
        atomicAdd(&stats[((size_t)b*4 + threadIdx.x)*2 + 0], (double)ssum[threadIdx.x]);
        atomicAdd(&stats[((size_t)b*4 + threadIdx.x)*2 + 1], (double)ssq[threadIdx.x]);
    }
}

// finalize full feature map
template<int Cout>
__global__ void k_fin(const float* __restrict__ mx, const float* __restrict__ mn,
                      const double* __restrict__ stats,
                      const float* __restrict__ gamma, const float* __restrict__ beta,
                      int Nq, float* __restrict__ fout) {
    int b = blockIdx.y;
    int t = blockIdx.x * blockDim.x + threadIdx.x;
    if (t >= Cout * Nq) return;
    int o = t / Nq, n = t % Nq;
    fout[((size_t)b*Cout + o)*Nq + n] = finval(mx, mn, stats, gamma, beta, b, n, o, Nq, Cout);
}

// finalize full + gather sampled
template<int Cout, int FB>
__global__ void k_finGather(const float* __restrict__ mx, const float* __restrict__ mn,
                            const double* __restrict__ stats,
                            const float* __restrict__ gamma, const float* __restrict__ beta,
                            int Nq, float* __restrict__ fout,
                            const float* __restrict__ srcc, const int* __restrict__ fpsi,
                            int S, float* __restrict__ dstc, float* __restrict__ dstf) {
    int b = blockIdx.y;
    if (blockIdx.x < FB) {
        int t = blockIdx.x * blockDim.x + threadIdx.x;
        if (t >= Cout * Nq) return;
        int o = t / Nq, n = t % Nq;
        fout[((size_t)b*Cout + o)*Nq + n] = finval(mx, mn, stats, gamma, beta, b, n, o, Nq, Cout);
    } else {
        int t = (blockIdx.x - FB) * blockDim.x + threadIdx.x;
        if (t >= (3 + Cout) * S) return;
        int c = t / S, s = t % S;
        int id = fpsi[(size_t)b*S + s];
        if (c < 3)
            dstc[((size_t)b*3 + c)*S + s] = srcc[((size_t)b*3 + c)*Nq + id];
        else
            dstf[((size_t)b*Cout + (c-3))*S + s] =
                finval(mx, mn, stats, gamma, beta, b, id, c-3, Nq, Cout);
    }
}

// stage-3 dual GEMM
template<int C, int Cout>
__global__ void k_gemm2(const float* __restrict__ f, const float* __restrict__ w,
                        int Nk, float* __restrict__ g, float* __restrict__ h) {
    constexpr int OC = Cout / 4;
    __shared__ float ws[2 * C * Cout];
    int b = blockIdx.y;
    for (int i = threadIdx.x; i < C * Cout; i += blockDim.x) {
        int c = i / Cout, o = i % Cout;
        float lo = w[o*2*C + c];
        float hi = w[o*2*C + C + c];
        ws[(2*c)*Cout + o]   = lo;
        ws[(2*c+1)*Cout + o] = hi - lo;
    }
    __syncthreads();
    int t = blockIdx.x * blockDim.x + threadIdx.x;
    int j = t / OC, oc = t % OC;
    if (j >= Nk) return;
    const float* fb = f + (size_t)b*C*Nk;
    float g0=0.f,g1=0.f,g2=0.f,g3=0.f, h0=0.f,h1=0.f,h2=0.f,h3=0.f;
#pragma unroll
    for (int c = 0; c < C; c++) {
        float fv = fb[(size_t)c*Nk + j];
        float4 wl = *(const float4*)&ws[(2*c)*Cout + oc*4];
        float4 wd = *(const float4*)&ws[(2*c+1)*Cout + oc*4];
        g0 += fv*wl.x; g1 += fv*wl.y; g2 += fv*wl.z; g3 += fv*wl.w;
        h0 += fv*wd.x; h1 += fv*wd.y; h2 += fv*wd.z; h3 += fv*wd.w;
    }
    size_t o4 = ((size_t)b*Nk + j)*Cout + oc*4;
    *(float4*)&g[o4] = make_float4(g0,g1,g2,g3);
    *(float4*)&h[o4] = make_float4(h0,h1,h2,h3);
}

// ---------------- launch ----------------
extern "C" void kernel_launch(void* const* d_in, const int* in_sizes, int n_in,
                              void* d_out, int out_size) {
    const float* x    = (const float*)d_in[0];
    const float* w_in = (const float*)d_in[1];
    const float* b_in = (const float*)d_in[2];
    const float* w1 = (const float*)d_in[3];
    const float* g1p = (const float*)d_in[4];
    const float* b1p = (const float*)d_in[5];
    const float* w2 = (const float*)d_in[6];
    const float* g2p = (const float*)d_in[7];
    const float* b2p = (const float*)d_in[8];
    const float* w3 = (const float*)d_in[9];
    const float* g3p = (const float*)d_in[10];
    const float* b3p = (const float*)d_in[11];
    const float* w4 = (const float*)d_in[12];
    const float* g4p = (const float*)d_in[13];
    const float* b4p = (const float*)d_in[14];

    float*  fb;  cudaGetSymbolAddress((void**)&fb,  d_fbuf);
    int*    ib;  cudaGetSymbolAddress((void**)&ib,  d_ibuf);
    double* st;  cudaGetSymbolAddress((void**)&st,  d_statsbuf);
    float*  out = (float*)d_out;

    float* g1  = fb + OFF_G1;  float* h1 = fb + OFF_H1;
    float* m1  = fb + OFF_M1;  float* mn1 = fb + OFF_MN1; float* f1 = fb + OFF_F1;
    float* cq1 = fb + OFF_CQ1; float* fq1 = fb + OFF_FQ1;
    float* g2  = fb + OFF_G2;  float* h2 = fb + OFF_H2;
    float* m2  = fb + OFF_M2;  float* mn2 = fb + OFF_MN2; float* f2 = fb + OFF_F2;
    float* g3  = fb + OFF_G3;  float* h3 = fb + OFF_H3;
    float* m3  = fb + OFF_M3;  float* mn3 = fb + OFF_MN3; float* f3 = fb + OFF_F3;
    float* fq3 = fb + OFF_FQ3;
    float* g4  = fb + OFF_G4;  float* h4 = fb + OFF_H4;
    float* m4  = fb + OFF_M4;  float* mn4 = fb + OFF_MN4;

    int* idx1 = ib + IOFF_IDX1; int* fps1 = ib + IOFF_FPS1;
    int* idx2 = ib + IOFF_IDX2; int* idx3 = ib + IOFF_IDX3;
    int* fps2 = ib + IOFF_FPS2; int* idx4 = ib + IOFF_IDX4;

    double* st1 = st + 0 * B * 8;
    double* st2 = st + 1 * B * 8;
    double* st3 = st + 2 * B * 8;
    double* st4 = st + 3 * B * 8;

    float* out_coor = out;                 // (B,3,128)
    float* out_f    = out + B * 3 * N2;    // (B,128,128)

    // 1: fps1 ∥ knn1 ∥ (lin+gemm1) ∥ stats zeroing
    k_megaA<<<32 + 8192 + 4 + 2048, 256>>>(x, w_in, b_in, w1, fps1, idx1, g1, h1, st);

    // 2-3: stage-1 stats, finalize + gather
    k_stats_max<32><<<dim3(CDIV(N0*8, 128), B), 128>>>(g1, h1, idx1, N0, N0, m1, mn1, st1);
    k_finGather<32, 256><<<dim3(256 + CDIV(35*N1, 256), B), 256>>>(
        m1, mn1, st1, g1p, b1p, N0, f1, x, fps1, N1, cq1, fq1);

    // 4: fps2 ∥ knn2 ∥ knn3 ∥ g2 ∥ h2
    k_megaB<<<32 + 2048 + 2048 + 4096 + 1024, 256>>>(cq1, x, f1, fq1, w2,
                                                     fps2, idx2, idx3, g2, h2);

    // 5-6: stage-2 stats + finalize
    k_stats_max<64><<<dim3(CDIV(N1*16, 128), B), 128>>>(g2, h2, idx2, N1, N0, m2, mn2, st2);
    k_fin<64><<<dim3(CDIV(64*N1, 256), B), 256>>>(m2, mn2, st2, g2p, b2p, N1, f2);

    // 7-9: stage 3
    k_gemm2<64, 64><<<dim3(CDIV(N1*16, 256), B), 256>>>(f2, w3, N1, g3, h3);
    k_stats_max<64><<<dim3(CDIV(N1*16, 128), B), 128>>>(g3, h3, idx3, N1, N1, m3, mn3, st3);
    k_finGather<64, 128><<<dim3(128 + CDIV(67*N2, 256), B), 256>>>(
        m3, mn3, st3, g3p, b3p, N1, f3, cq1, fps2, N2, out_coor, fq3);

    // 10-12: stage 4
    k_megaC<<<512 + 2048 + 512, 256>>>(out_coor, cq1, f3, fq3, w4, idx4, g4, h4);
    k_stats_max<128><<<dim3(CDIV(N2*32, 128), B), 128>>>(g4, h4, idx4, N2, N1, m4, mn4, st4);
    k_fin<128><<<dim3(CDIV(128*N2, 256), B), 256>>>(m4, mn4, st4, g4p, b4p, N2, out_f);
}

// round 8
// speedup vs baseline: 2.6887x; 1.0813x over previous
#include <cuda_runtime.h>
#include <math.h>

#define CDIV(a,b) (((a)+(b)-1)/(b))

static constexpr int B  = 32;
static constexpr int KN = 16;
static constexpr int N0 = 2048, N1 = 512, N2 = 128;

// ---------------- scratch ----------------
static constexpr size_t OFF_G1  = 0;                                  // B*N0*32
static constexpr size_t OFF_H1  = OFF_G1  + (size_t)B*N0*32;
static constexpr size_t OFF_M1  = OFF_H1  + (size_t)B*N0*32;
static constexpr size_t OFF_MN1 = OFF_M1  + (size_t)B*N0*32;
static constexpr size_t OFF_F1  = OFF_MN1 + (size_t)B*N0*32;          // B*32*N0
static constexpr size_t OFF_CQ1 = OFF_F1  + (size_t)B*32*N0;          // B*3*N1
static constexpr size_t OFF_FQ1 = OFF_CQ1 + (size_t)B*3*N1;           // B*32*N1
static constexpr size_t OFF_G2  = OFF_FQ1 + (size_t)B*32*N1;          // B*N0*64
static constexpr size_t OFF_H2  = OFF_G2  + (size_t)B*N0*64;          // B*N1*64
static constexpr size_t OFF_M2  = OFF_H2  + (size_t)B*N1*64;
static constexpr size_t OFF_MN2 = OFF_M2  + (size_t)B*N1*64;
static constexpr size_t OFF_F2  = OFF_MN2 + (size_t)B*N1*64;          // B*64*N1
static constexpr size_t OFF_G3  = OFF_F2  + (size_t)B*64*N1;
static constexpr size_t OFF_H3  = OFF_G3  + (size_t)B*N1*64;
static constexpr size_t OFF_M3  = OFF_H3  + (size_t)B*N1*64;
static constexpr size_t OFF_MN3 = OFF_M3  + (size_t)B*N1*64;
static constexpr size_t OFF_F3  = OFF_MN3 + (size_t)B*N1*64;          // B*64*N1
static constexpr size_t OFF_FQ3 = OFF_F3  + (size_t)B*64*N1;          // B*64*N2
static constexpr size_t OFF_G4  = OFF_FQ3 + (size_t)B*64*N2;          // B*N1*128
static constexpr size_t OFF_H4  = OFF_G4  + (size_t)B*N1*128;         // B*N2*128
static constexpr size_t OFF_M4  = OFF_H4  + (size_t)B*N2*128;
static constexpr size_t OFF_MN4 = OFF_M4  + (size_t)B*N2*128;
static constexpr size_t FBUF_TOTAL = OFF_MN4 + (size_t)B*N2*128;

__device__ float d_fbuf[FBUF_TOTAL];

static constexpr size_t IOFF_IDX1 = 0;
static constexpr size_t IOFF_FPS1 = IOFF_IDX1 + (size_t)B*N0*KN;
static constexpr size_t IOFF_IDX2 = IOFF_FPS1 + (size_t)B*N1;
static constexpr size_t IOFF_IDX3 = IOFF_IDX2 + (size_t)B*N1*KN;
static constexpr size_t IOFF_FPS2 = IOFF_IDX3 + (size_t)B*N1*KN;
static constexpr size_t IOFF_IDX4 = IOFF_FPS2 + (size_t)B*N2;
static constexpr size_t IBUF_TOTAL = IOFF_IDX4 + (size_t)B*N2*KN;

__device__ int d_ibuf[IBUF_TOTAL];
__device__ double d_statsbuf[4 * B * 4 * 2];   // [layer][b][group][{sum,sumsq}]

// ---------------- device helpers ----------------

// Warp-cooperative KNN: ONE QUERY PER WARP; 8 queries per 256-thread block.
// Lane l<16 holds the l-th smallest (dist,idx), sorted ascending.
// Seed: full-warp bitonic sort of first 32 (d,j) pairs by lexicographic (d,j)
// (== jax.lax.top_k stable tie rule); lanes 0-15 keep the smallest 16.
// Main loop from j0=32 with the 16th-best threshold carried in a register.
__device__ __forceinline__ void dev_knn(int NK, const float* __restrict__ cq,
                                        const float* __restrict__ ck,
                                        int Nq, int* __restrict__ idx_out,
                                        int qblk, int b, char* sraw) {
    float4* skey = (float4*)sraw;
    const float* ckb = ck + (size_t)b*3*NK;
    for (int j = threadIdx.x; j < NK; j += 256) {
        float kx = ckb[j], ky = ckb[NK + j], kz = ckb[2*NK + j];
        skey[j] = make_float4(-2.f*kx, -2.f*ky, -2.f*kz, kx*kx + ky*ky + kz*kz);
    }
    __syncthreads();
    int w = threadIdx.x >> 5, lane = threadIdx.x & 31;
    int q = qblk * 8 + w;
    const float* cqb = cq + (size_t)b*3*Nq;
    float qx = cqb[q], qy = cqb[Nq + q], qz = cqb[2*Nq + q];

    // ---- seed: bitonic sort of keys 0..31 by (d, j) ascending ----
    float bd; int bj;
    {
        float4 kk = skey[lane];
        bd = fmaf(kk.x, qx, fmaf(kk.y, qy, fmaf(kk.z, qz, kk.w)));
        bj = lane;
#pragma unroll
        for (int k = 2; k <= 32; k <<= 1) {
#pragma unroll
            for (int s2 = k >> 1; s2 > 0; s2 >>= 1) {
                float pd = __shfl_xor_sync(0xffffffffu, bd, s2);
                int   pj = __shfl_xor_sync(0xffffffffu, bj, s2);
                bool asc    = ((lane & k)  == 0) || (k == 32);
                bool lower  = ((lane & s2) == 0);
                bool pLess  = (pd < bd) || (pd == bd && pj < bj);
                bool take   = ((asc == lower) == pLess);
                bd = take ? pd : bd;
                bj = take ? pj : bj;
            }
        }
    }
    float th = __shfl_sync(0xffffffffu, bd, 15);   // current 16th best

    // ---- main scan ----
    for (int j0 = 32; j0 < NK; j0 += 32) {
        float4 kk = skey[j0 + lane];
        float d = fmaf(kk.x, qx, fmaf(kk.y, qy, fmaf(kk.z, qz, kk.w)));
        unsigned hits = __ballot_sync(0xffffffffu, d < th);
        while (hits) {
            int s = __ffs(hits) - 1;          // lowest lane first => ascending j
            hits &= hits - 1;
            float dd = __shfl_sync(0xffffffffu, d, s);
            if (dd < th) {                    // th warp-uniform register
                int r = __popc(__ballot_sync(0xffffffffu, bd <= dd) & 0xFFFFu);
                float pd = __shfl_up_sync(0xffffffffu, bd, 1);
                int   pj = __shfl_up_sync(0xffffffffu, bj, 1);
                if (lane > r && lane < 16) { bd = pd; bj = pj; }
                if (lane == r)             { bd = dd; bj = j0 + s; }
                th = __shfl_sync(0xffffffffu, bd, 15);
            }
        }
    }
    if (lane < 16) idx_out[((size_t)b*Nq + q)*KN + lane] = bj;
}

// FPS, 256 threads, one barrier/iter, packed-u64 block merge (proven).
template<int N, int S>
__device__ __forceinline__ void dev_fps(const float* __restrict__ coor,
                                        int* __restrict__ out, int b, char* sraw) {
    constexpr int BLK = 256, PPT = N / BLK, NW = BLK / 32;
    float* sx = (float*)sraw;
    float* sy = sx + N;
    float* sz = sy + N;
    unsigned long long* spk = (unsigned long long*)(sz + N);  // [2][NW]
    int t = threadIdx.x, lane = t & 31, w = t >> 5;
    const float* cb = coor + (size_t)b*3*N;

    float px[PPT], py[PPT], pz[PPT], dist[PPT];
#pragma unroll
    for (int p = 0; p < PPT; p++) {
        int i = t + p * BLK;
        float vx = cb[i], vy = cb[N + i], vz = cb[2*N + i];
        px[p] = vx; py[p] = vy; pz[p] = vz;
        sx[i] = vx; sy[i] = vy; sz[i] = vz;
        dist[p] = 1e10f;
    }
    __syncthreads();

    int last = 0;
    for (int s = 0; s < S; s++) {
        if (t == 0) out[(size_t)b*S + s] = last;
        float cx = sx[last], cy = sy[last], cz = sz[last];
        float bv = -1.0f; int bidx = 0;
#pragma unroll
        for (int p = 0; p < PPT; p++) {
            float dx = px[p]-cx, dy = py[p]-cy, dz = pz[p]-cz;
            float d = dx*dx + dy*dy + dz*dz;
            float nd = fminf(dist[p], d);
            dist[p] = nd;
            if (nd > bv) { bv = nd; bidx = t + p * BLK; }
        }
        unsigned bits = __float_as_uint(fmaxf(bv, 0.0f));
        unsigned m  = __reduce_max_sync(0xffffffffu, bits);
        unsigned ci = (bits == m) ? (unsigned)bidx : 0xffffffffu;
        unsigned mi = __reduce_min_sync(0xffffffffu, ci);
        int buf = (s & 1) * NW;
        if (lane == 0)
            spk[buf + w] = ((unsigned long long)m << 32) | (unsigned)(~mi);
        __syncthreads();
        unsigned long long best = spk[buf + 0];
#pragma unroll
        for (int i2 = 1; i2 < NW; i2++) {
            unsigned long long v = spk[buf + i2];
            best = (v > best) ? v : best;
        }
        last = (int)(~(unsigned)best);
    }
}

// GEMM body, 256 threads: out[b,j,o] = sum_c wsel[o,c]*f[b,c,j]
template<int C, int Cout>
__device__ __forceinline__ void dev_gemm(const float* __restrict__ f,
                                         const float* __restrict__ w,
                                         int Nk, float* __restrict__ out,
                                         bool diff, int bq, int b, float* ws) {
    constexpr int OC = Cout / 4;
    for (int i = threadIdx.x; i < C * Cout; i += 256) {
        int c = i / Cout, o = i % Cout;
        float lo = w[o*2*C + c];
        float hi = w[o*2*C + C + c];
        ws[c*Cout + o] = diff ? (hi - lo) : lo;
    }
    __syncthreads();
    int t = bq * 256 + threadIdx.x;
    int j = t / OC, oc = t % OC;
    if (j >= Nk) return;
    const float* fb = f + (size_t)b*C*Nk;
    float a0 = 0.f, a1 = 0.f, a2 = 0.f, a3 = 0.f;
#pragma unroll
    for (int c = 0; c < C; c++) {
        float fv = fb[(size_t)c*Nk + j];
        float4 wv = *(const float4*)&ws[c*Cout + oc*4];
        a0 += fv * wv.x; a1 += fv * wv.y; a2 += fv * wv.z; a3 += fv * wv.w;
    }
    *(float4*)&out[((size_t)b*Nk + j)*Cout + oc*4] = make_float4(a0, a1, a2, a3);
}

// fused input-linear + stage-1 dual GEMM (proven).
__device__ __forceinline__ void dev_gemmIn(const float* __restrict__ x,
                                           const float* __restrict__ w_in,
                                           const float* __restrict__ b_in,
                                           const float* __restrict__ w1,
                                           float* __restrict__ g1, float* __restrict__ h1,
                                           int r, float* ws) {
    float* wlo = ws; float* wdf = ws + 256; float* win = ws + 512; float* bin = ws + 536;
    int t = threadIdx.x;
    if (t < 256) {
        int o = t & 31, c = t >> 5;
        float lo = w1[o*16 + c];
        float hi = w1[o*16 + 8 + c];
        wlo[c*32 + o] = lo;
        wdf[c*32 + o] = hi - lo;
    }
    if (t < 24) win[t] = w_in[t];
    if (t < 8)  bin[t] = b_in[t];
    __syncthreads();
    int b = r >> 6, jb = r & 63;
    int oc = t & 7, jo = t >> 3;
    int j = jb * 32 + jo;
    float x0 = x[((size_t)b*3+0)*N0 + j];
    float x1 = x[((size_t)b*3+1)*N0 + j];
    float x2 = x[((size_t)b*3+2)*N0 + j];
    float f0[8];
#pragma unroll
    for (int o = 0; o < 8; o++)
        f0[o] = win[o*3+0]*x0 + win[o*3+1]*x1 + win[o*3+2]*x2 + bin[o];
    float g0=0.f,g1v=0.f,g2v=0.f,g3v=0.f, h0=0.f,h1v=0.f,h2v=0.f,h3v=0.f;
#pragma unroll
    for (int c = 0; c < 8; c++) {
        float fv = f0[c];
        float4 wl = *(const float4*)&wlo[c*32 + oc*4];
        float4 wd = *(const float4*)&wdf[c*32 + oc*4];
        g0 += fv*wl.x; g1v += fv*wl.y; g2v += fv*wl.z; g3v += fv*wl.w;
        h0 += fv*wd.x; h1v += fv*wd.y; h2v += fv*wd.z; h3v += fv*wd.w;
    }
    size_t o4 = ((size_t)b*N0 + j)*32 + oc*4;
    *(float4*)&g1[o4] = make_float4(g0,g1v,g2v,g3v);
    *(float4*)&h1[o4] = make_float4(h0,h1v,h2v,h3v);
}

// finalize value for one (b,n,o)
__device__ __forceinline__ float finval(const float* __restrict__ mx, const float* __restrict__ mn,
                                        const double* __restrict__ st,
                                        const float* __restrict__ gamma, const float* __restrict__ beta,
                                        int b, int n, int o, int Nq, int C) {
    int grp = o / (C / 4);
    double cnt = (double)(C / 4) * (double)Nq * (double)KN;
    double su = st[((size_t)b*4 + grp)*2 + 0];
    double sq = st[((size_t)b*4 + grp)*2 + 1];
    double m  = su / cnt;
    double vr = sq / cnt - m * m;
    float mean = (float)m;
    float rstd = rsqrtf((float)vr + 1e-5f);
    float ga = gamma[o], be = beta[o];
    float sel = (ga >= 0.f) ? mx[((size_t)b*Nq + n)*C + o]
                            : mn[((size_t)b*Nq + n)*C + o];
    float v = (sel - mean) * rstd * ga + be;
    return (v >= 0.f) ? v : 0.2f * v;
}

// ---------------- kernels ----------------

// megaA: [0,32) fps1; [32,8224) knn1 (warp/query); [8224,8228) zero; [8228,10276) gemmIn
__global__ __launch_bounds__(256) void k_megaA(const float* __restrict__ x,
                                               const float* __restrict__ w_in,
                                               const float* __restrict__ b_in,
                                               const float* __restrict__ w1,
                                               int* __restrict__ fps1,
                                               int* __restrict__ idx1,
                                               float* __restrict__ g1,
                                               float* __restrict__ h1,
                                               double* __restrict__ st) {
    __shared__ __align__(16) char sraw[33792];
    int bid = blockIdx.x;
    if (bid < 32) {
        dev_fps<N0, N1>(x, fps1, bid, sraw);
    } else if (bid < 32 + 8192) {
        int r = bid - 32;
        dev_knn(N0, x, x, N0, idx1, r & 255, r >> 8, sraw);
    } else if (bid < 32 + 8192 + 4) {
        st[(bid - 8224) * 256 + threadIdx.x] = 0.0;
    } else {
        dev_gemmIn(x, w_in, b_in, w1, g1, h1, bid - 8228, (float*)sraw);
    }
}

// megaB: [0,32) fps2; [32,2080) knn2; [2080,4128) knn3; [4128,8224) g2; [8224,9248) h2
__global__ __launch_bounds__(256) void k_megaB(const float* __restrict__ cq1,
                                               const float* __restrict__ x,
                                               const float* __restrict__ f1,
                                               const float* __restrict__ fq1,
                                               const float* __restrict__ w2,
                                               int* __restrict__ fps2,
                                               int* __restrict__ idx2,
                                               int* __restrict__ idx3,
                                               float* __restrict__ g2,
                                               float* __restrict__ h2) {
    __shared__ __align__(16) char sraw[33792];
    int bid = blockIdx.x;
    if (bid < 32) {
        dev_fps<N1, N2>(cq1, fps2, bid, sraw);
    } else if (bid < 2080) {
        int r = bid - 32;
        dev_knn(N0, cq1, x, N1, idx2, r & 63, r >> 6, sraw);
    } else if (bid < 4128) {
        int r = bid - 2080;
        dev_knn(N1, cq1, cq1, N1, idx3, r & 63, r >> 6, sraw);
    } else if (bid < 8224) {
        int r = bid - 4128;
        dev_gemm<32, 64>(f1, w2, N0, g2, false, r & 127, r >> 7, (float*)sraw);
    } else {
        int r = bid - 8224;
        dev_gemm<32, 64>(fq1, w2, N1, h2, true, r & 31, r >> 5, (float*)sraw);
    }
}

// megaC: [0,512) knn4; [512,2560) g4; [2560,3072) h4
__global__ __launch_bounds__(256) void k_megaC(const float* __restrict__ out_coor,
                                               const float* __restrict__ cq1,
                                               const float* __restrict__ f3,
                                               const float* __restrict__ fq3,
                                               const float* __restrict__ w4,
                                               int* __restrict__ idx4,
                                               float* __restrict__ g4,
                                               float* __restrict__ h4) {
    __shared__ __align__(16) char sraw[33792];
    int bid = blockIdx.x;
    if (bid < 512) {
        int r = bid;
        dev_knn(N1, out_coor, cq1, N2, idx4, r & 15, r >> 4, sraw);
    } else if (bid < 512 + 2048) {
        int r = bid - 512;
        dev_gemm<64, 128>(f3, w4, N1, g4, false, r & 63, r >> 6, (float*)sraw);
    } else {
        int r = bid - 2560;
        dev_gemm<64, 128>(fq3, w4, N2, h4, true, r & 15, r >> 4, (float*)sraw);
    }
}

// fused stats+max
template<int Cout>
__global__ void k_stats_max(const float* __restrict__ g, const float* __restrict__ h,
                            const int* __restrict__ idx, int Nq, int Nk,
                            float* __restrict__ mx, float* __restrict__ mn,
                            double* __restrict__ stats) {
    constexpr int OC = Cout / 4;
    __shared__ float ssum[4], ssq[4];
    int b = blockIdx.y;
    if (threadIdx.x < 4) { ssum[threadIdx.x] = 0.f; ssq[threadIdx.x] = 0.f; }
    __syncthreads();
    int t = blockIdx.x * blockDim.x + threadIdx.x;
    int n = t / OC, oc = t % OC;
    float s = 0.f, ss = 0.f;
    int grp = 0;
    if (n < Nq) {
        grp = (oc * 16) / Cout;
        const int4* ib4 = (const int4*)(idx + ((size_t)b*Nq + n) * KN);
        int jj[KN];
#pragma unroll
        for (int u = 0; u < 4; u++) {
            int4 v = ib4[u];
            jj[u*4+0] = v.x; jj[u*4+1] = v.y; jj[u*4+2] = v.z; jj[u*4+3] = v.w;
        }
        float4 hv = *(const float4*)&h[((size_t)b*Nq + n)*Cout + oc*4];
        float4 m4 = make_float4(-3.4e38f, -3.4e38f, -3.4e38f, -3.4e38f);
        float4 n4 = make_float4( 3.4e38f,  3.4e38f,  3.4e38f,  3.4e38f);
#pragma unroll
        for (int k = 0; k < KN; k++) {
            float4 gv = *(const float4*)&g[((size_t)b*Nk + jj[k])*Cout + oc*4];
            float y0 = gv.x + hv.x, y1 = gv.y + hv.y, y2 = gv.z + hv.z, y3 = gv.w + hv.w;
            m4.x = fmaxf(m4.x, y0); m4.y = fmaxf(m4.y, y1);
            m4.z = fmaxf(m4.z, y2); m4.w = fmaxf(m4.w, y3);
            n4.x = fminf(n4.x, y0); n4.y = fminf(n4.y, y1);
            n4.z = fminf(n4.z, y2); n4.w = fminf(n4.w, y3);
            s  += (y0 + y1) + (y2 + y3);
            ss += (y0*y0 + y1*y1) + (y2*y2 + y3*y3);
        }
        *(float4*)&mx[((size_t)b*Nq + n)*Cout + oc*4] = m4;
        *(float4*)&mn[((size_t)b*Nq + n)*Cout + oc*4] = n4;
    }
    atomicAdd(&ssum[grp], s);
    atomicAdd(&ssq[grp], ss);
    __syncthreads();
    if (threadIdx.x < 4) {
        atomicAdd(&stats[((size_t)b*4 + threadIdx.x)*2 + 0], (double)ssum[threadIdx.x]);
        atomicAdd(&stats[((size_t)b*4 + threadIdx.x)*2 + 1], (double)ssq[threadIdx.x]);
    }
}

// finalize full feature map
template<int Cout>
__global__ void k_fin(const float* __restrict__ mx, const float* __restrict__ mn,
                      const double* __restrict__ stats,
                      const float* __restrict__ gamma, const float* __restrict__ beta,
                      int Nq, float* __restrict__ fout) {
    int b = blockIdx.y;
    int t = blockIdx.x * blockDim.x + threadIdx.x;
    if (t >= Cout * Nq) return;
    int o = t / Nq, n = t % Nq;
    fout[((size_t)b*Cout + o)*Nq + n] = finval(mx, mn, stats, gamma, beta, b, n, o, Nq, Cout);
}

// finalize full + gather sampled
template<int Cout, int FB>
__global__ void k_finGather(const float* __restrict__ mx, const float* __restrict__ mn,
                            const double* __restrict__ stats,
                            const float* __restrict__ gamma, const float* __restrict__ beta,
                            int Nq, float* __restrict__ fout,
                            const float* __restrict__ srcc, const int* __restrict__ fpsi,
                            int S, float* __restrict__ dstc, float* __restrict__ dstf) {
    int b = blockIdx.y;
    if (blockIdx.x < FB) {
        int t = blockIdx.x * blockDim.x + threadIdx.x;
        if (t >= Cout * Nq) return;
        int o = t / Nq, n = t % Nq;
        fout[((size_t)b*Cout + o)*Nq + n] = finval(mx, mn, stats, gamma, beta, b, n, o, Nq, Cout);
    } else {
        int t = (blockIdx.x - FB) * blockDim.x + threadIdx.x;
        if (t >= (3 + Cout) * S) return;
        int c = t / S, s = t % S;
        int id = fpsi[(size_t)b*S + s];
        if (c < 3)
            dstc[((size_t)b*3 + c)*S + s] = srcc[((size_t)b*3 + c)*Nq + id];
        else
            dstf[((size_t)b*Cout + (c-3))*S + s] =
                finval(mx, mn, stats, gamma, beta, b, id, c-3, Nq, Cout);
    }
}

// stage-3 dual GEMM
template<int C, int Cout>
__global__ void k_gemm2(const float* __restrict__ f, const float* __restrict__ w,
                        int Nk, float* __restrict__ g, float* __restrict__ h) {
    constexpr int OC = Cout / 4;
    __shared__ float ws[2 * C * Cout];
    int b = blockIdx.y;
    for (int i = threadIdx.x; i < C * Cout; i += blockDim.x) {
        int c = i / Cout, o = i % Cout;
        float lo = w[o*2*C + c];
        float hi = w[o*2*C + C + c];
        ws[(2*c)*Cout + o]   = lo;
        ws[(2*c+1)*Cout + o] = hi - lo;
    }
    __syncthreads();
    int t = blockIdx.x * blockDim.x + threadIdx.x;
    int j = t / OC, oc = t % OC;
    if (j >= Nk) return;
    const float* fb = f + (size_t)b*C*Nk;
    float g0=0.f,g1=0.f,g2=0.f,g3=0.f, h0=0.f,h1=0.f,h2=0.f,h3=0.f;
#pragma unroll
    for (int c = 0; c < C; c++) {
        float fv = fb[(size_t)c*Nk + j];
        float4 wl = *(const float4*)&ws[(2*c)*Cout + oc*4];
        float4 wd = *(const float4*)&ws[(2*c+1)*Cout + oc*4];
        g0 += fv*wl.x; g1 += fv*wl.y; g2 += fv*wl.z; g3 += fv*wl.w;
        h0 += fv*wd.x; h1 += fv*wd.y; h2 += fv*wd.z; h3 += fv*wd.w;
    }
    size_t o4 = ((size_t)b*Nk + j)*Cout + oc*4;
    *(float4*)&g[o4] = make_float4(g0,g1,g2,g3);
    *(float4*)&h[o4] = make_float4(h0,h1,h2,h3);
}

// ---------------- launch ----------------
extern "C" void kernel_launch(void* const* d_in, const int* in_sizes, int n_in,
                              void* d_out, int out_size) {
    const float* x    = (const float*)d_in[0];
    const float* w_in = (const float*)d_in[1];
    const float* b_in = (const float*)d_in[2];
    const float* w1 = (const float*)d_in[3];
    const float* g1p = (const float*)d_in[4];
    const float* b1p = (const float*)d_in[5];
    const float* w2 = (const float*)d_in[6];
    const float* g2p = (const float*)d_in[7];
    const float* b2p = (const float*)d_in[8];
    const float* w3 = (const float*)d_in[9];
    const float* g3p = (const float*)d_in[10];
    const float* b3p = (const float*)d_in[11];
    const float* w4 = (const float*)d_in[12];
    const float* g4p = (const float*)d_in[13];
    const float* b4p = (const float*)d_in[14];

    float*  fb;  cudaGetSymbolAddress((void**)&fb,  d_fbuf);
    int*    ib;  cudaGetSymbolAddress((void**)&ib,  d_ibuf);
    double* st;  cudaGetSymbolAddress((void**)&st,  d_statsbuf);
    float*  out = (float*)d_out;

    float* g1  = fb + OFF_G1;  float* h1 = fb + OFF_H1;
    float* m1  = fb + OFF_M1;  float* mn1 = fb + OFF_MN1; float* f1 = fb + OFF_F1;
    float* cq1 = fb + OFF_CQ1; float* fq1 = fb + OFF_FQ1;
    float* g2  = fb + OFF_G2;  float* h2 = fb + OFF_H2;
    float* m2  = fb + OFF_M2;  float* mn2 = fb + OFF_MN2; float* f2 = fb + OFF_F2;
    float* g3  = fb + OFF_G3;  float* h3 = fb + OFF_H3;
    float* m3  = fb + OFF_M3;  float* mn3 = fb + OFF_MN3; float* f3 = fb + OFF_F3;
    float* fq3 = fb + OFF_FQ3;
    float* g4  = fb + OFF_G4;  float* h4 = fb + OFF_H4;
    float* m4  = fb + OFF_M4;  float* mn4 = fb + OFF_MN4;

    int* idx1 = ib + IOFF_IDX1; int* fps1 = ib + IOFF_FPS1;
    int* idx2 = ib + IOFF_IDX2; int* idx3 = ib + IOFF_IDX3;
    int* fps2 = ib + IOFF_FPS2; int* idx4 = ib + IOFF_IDX4;

    double* st1 = st + 0 * B * 8;
    double* st2 = st + 1 * B * 8;
    double* st3 = st + 2 * B * 8;
    double* st4 = st + 3 * B * 8;

    float* out_coor = out;                 // (B,3,128)
    float* out_f    = out + B * 3 * N2;    // (B,128,128)

    // 1: fps1 ∥ knn1 ∥ (lin+gemm1) ∥ stats zeroing
    k_megaA<<<32 + 8192 + 4 + 2048, 256>>>(x, w_in, b_in, w1, fps1, idx1, g1, h1, st);

    // 2-3: stage-1 stats, finalize + gather
    k_stats_max<32><<<dim3(CDIV(N0*8, 128), B), 128>>>(g1, h1, idx1, N0, N0, m1, mn1, st1);
    k_finGather<32, 256><<<dim3(256 + CDIV(35*N1, 256), B), 256>>>(
        m1, mn1, st1, g1p, b1p, N0, f1, x, fps1, N1, cq1, fq1);

    // 4: fps2 ∥ knn2 ∥ knn3 ∥ g2 ∥ h2
    k_megaB<<<32 + 2048 + 2048 + 4096 + 1024, 256>>>(cq1, x, f1, fq1, w2,
                                                     fps2, idx2, idx3, g2, h2);

    // 5-6: stage-2 stats + finalize
    k_stats_max<64><<<dim3(CDIV(N1*16, 128), B), 128>>>(g2, h2, idx2, N1, N0, m2, mn2, st2);
    k_fin<64><<<dim3(CDIV(64*N1, 256), B), 256>>>(m2, mn2, st2, g2p, b2p, N1, f2);

    // 7-9: stage 3
    k_gemm2<64, 64><<<dim3(CDIV(N1*16, 256), B), 256>>>(f2, w3, N1, g3, h3);
    k_stats_max<64><<<dim3(CDIV(N1*16, 128), B), 128>>>(g3, h3, idx3, N1, N1, m3, mn3, st3);
    k_finGather<64, 128><<<dim3(128 + CDIV(67*N2, 256), B), 256>>>(
        m3, mn3, st3, g3p, b3p, N1, f3, cq1, fps2, N2, out_coor, fq3);

    // 10-12: stage 4
    k_megaC<<<512 + 2048 + 512, 256>>>(out_coor, cq1, f3, fq3, w4, idx4, g4, h4);
    k_stats_max<128><<<dim3(CDIV(N2*32, 128), B), 128>>>(g4, h4, idx4, N2, N1, m4, mn4, st4);
    k_fin<128><<<dim3(CDIV(128*N2, 256), B), 256>>>(m4, mn4, st4, g4p, b4p, N2, out_f);
}